// round 15
// baseline (speedup 1.0000x reference)
#include <cuda_runtime.h>
#include <math.h>

typedef unsigned long long ull;
typedef unsigned int u32;

#define Sn    64
#define Bz    256
#define VIN   128
#define VOUTn 128
#define UU    1024
#define EE    512
#define TDEC  25
#define G3U   3072
#define NQP   4224            // [gh(3072) | q(1024) | pred(128)]
#define GHKS  6
#define GIKS  6
#define QGHKS 4
#define KT_U   (3*UU)         // tf32 pair-concat K: [hi|hi|lo] x [hi|lo|hi]
#define KT_VIN (3*VIN)
#define KT_E   (3*EE)

// ---------------- fp32 scratch ----------------
__device__ __align__(16) float g_gi_enc[(size_t)Sn*Bz*G3U];
__device__ __align__(16) float g_enc_out[(size_t)Sn*Bz*UU];
__device__ __align__(16) float g_enc_proj[(size_t)Sn*Bz*UU];
__device__ __align__(16) float g_h[Bz*UU];
__device__ __align__(16) float g_ghp[(size_t)GHKS*Bz*G3U];
__device__ __align__(16) float g_gip[(size_t)GIKS*Bz*G3U];
__device__ __align__(16) float g_qghp[(size_t)QGHKS*Bz*NQP];
__device__ int   g_idx[Bz];
__device__ __align__(16) float g_Wqgh[(size_t)NQP*UU];
__device__ __align__(16) float g_bqgh[NQP];
__device__ __align__(16) float g_T[(size_t)VOUTn*G3U];
__device__ __align__(16) float g_Aemb[VOUTn*EE];
__device__ __align__(16) float g_zero[NQP];

// ---------------- tf32 limb-pair scratch (A-mode [hi|hi|lo], W-mode [hi|lo|hi]) --
__device__ __align__(16) float g_xt   [(size_t)Sn*Bz*KT_VIN];
__device__ __align__(16) float g_Wiht [(size_t)G3U*KT_VIN];
__device__ __align__(16) float g_Whht [(size_t)G3U*KT_U];
__device__ __align__(16) float g_Wqght[(size_t)NQP*KT_U];
__device__ __align__(16) float g_Wdct [(size_t)G3U*KT_U];
__device__ __align__(16) float g_Wdet [(size_t)G3U*KT_E];
__device__ __align__(16) float g_W1t  [(size_t)UU*KT_U];
__device__ __align__(16) float g_Aembt[(size_t)VOUTn*KT_E];
__device__ __align__(16) float g_ht   [(size_t)Bz*KT_U];
__device__ __align__(16) float g_eot  [(size_t)Sn*Bz*KT_U];
__device__ __align__(16) float g_ctxt [(size_t)Bz*KT_U];

// ---------------- fast (~1e-7) transcendentals ----------------
__device__ __forceinline__ float f_ex2(float x){ float r; asm("ex2.approx.f32 %0, %1;" : "=f"(r) : "f"(x)); return r; }
__device__ __forceinline__ float f_rcp(float x){ float r; asm("rcp.approx.f32 %0, %1;" : "=f"(r) : "f"(x)); return r; }
__device__ __forceinline__ float fsigm(float x){ return f_rcp(1.f + f_ex2(-1.4426950408889634f*x)); }
__device__ __forceinline__ float ftanh(float x){ return 1.f - 2.f*f_rcp(1.f + f_ex2(2.8853900817779268f*x)); }

__device__ __forceinline__ float tf32f(float a) {
    u32 u; asm("cvt.rna.tf32.f32 %0, %1;" : "=r"(u) : "f"(a));
    return __uint_as_float(u);
}
__device__ __forceinline__ u32 s2u(const void* p) {
    u32 a; asm("{ .reg .u64 t; cvta.to.shared.u64 t, %1; cvt.u32.u64 %0, t; }" : "=r"(a) : "l"(p));
    return a;
}

#define LDMX4(r0, r1, r2, r3, addr) \
    asm volatile("ldmatrix.sync.aligned.m8n8.x4.shared.b16 {%0,%1,%2,%3}, [%4];" \
        : "=r"(r0), "=r"(r1), "=r"(r2), "=r"(r3) : "r"(addr))

#define MMATF(d, a, b0, b1) \
    asm volatile("mma.sync.aligned.m16n8k8.row.col.f32.tf32.tf32.f32 " \
        "{%0,%1,%2,%3}, {%4,%5,%6,%7}, {%8,%9}, {%0,%1,%2,%3};" \
        : "+f"((d)[0]), "+f"((d)[1]), "+f"((d)[2]), "+f"((d)[3]) \
        : "r"((a)[0]), "r"((a)[1]), "r"((a)[2]), "r"((a)[3]), "r"(b0), "r"(b1))

// ------- tf32 mma.sync GEMM: C[M,N] = A'[M,Kt] @ W'[N,Kt]^T (+bias on z==0) -----
// A' = [hi|hi|lo], W' = [hi|lo|hi] (Kt = 3K) => sum of hi*hi + hi*lo + lo*hi.
// 128x128 tile/CTA, 256 thr (8 warps 2x4), warp 64x32, m16n8k8 tf32, fp32 acc.
// 32-k chunks: 128 rows x 128B, XOR-swizzled 16B (=4 tf32 = 1 ldmatrix row).
// grid=(N/128, M/128, KS); slice z -> C + z*M*N over its chunk range.
// sorted-x_len early exit: tstep>=0: rows=batch; tstep<0: rows=s*256+b.
__global__ void __launch_bounds__(256) gemmt(
    const float* __restrict__ A, const float* __restrict__ W,
    const float* __restrict__ bias, float* __restrict__ C,
    int M, int N, int Kt, int KS,
    const int* __restrict__ x_len, int tstep)
{
    const int bm = blockIdx.y * 128;
    if (x_len) {
        int t_eff = (tstep >= 0) ? tstep : (bm >> 8);
        int b_hi  = (tstep >= 0) ? (bm + 127) : ((bm & 255) + 127);
        if (x_len[b_hi] <= t_eff) return;
    }
    __shared__ __align__(16) char smA[16384];   // 128 rows x 32 tf32 (128B)
    __shared__ __align__(16) char smB[16384];

    const int tid  = threadIdx.x;
    const int wid  = tid >> 5;
    const int lane = tid & 31;
    const int wm   = (wid >> 2) << 6;        // 0 / 64
    const int wn   = (wid & 3) << 5;         // 0..96
    const int bn   = blockIdx.x * 128;

    const int z  = blockIdx.z;
    const int NC = Kt >> 5;                   // 32-k chunks
    const int c0 = (NC * z) / KS, c1 = (NC * (z + 1)) / KS;
    C += (size_t)z * M * N;

    float acc[4][4][4];
    #pragma unroll
    for (int i = 0; i < 4; i++)
        #pragma unroll
        for (int j = 0; j < 4; j++)
            #pragma unroll
            for (int r = 0; r < 4; r++) acc[i][j][r] = 0.f;

    const int lrow  = tid >> 1;               // 0..127
    const int lhalf = (tid & 1) << 2;         // chunk 0 or 4
    const int lr15  = lane & 15;
    const int lc16  = lane >> 4;              // 0/1
    const u32 abase = s2u(smA);
    const u32 bbase = s2u(smB);

    const float* gA = A + (size_t)(bm + lrow) * Kt;
    const float* gW = W + (size_t)(bn + lrow) * Kt;
    const int sw0 = lrow * 128;
    const int swm = lrow & 7;

    for (int ic = c0; ic < c1; ic++) {
        // ---- stage one 32-k chunk of A and B (16 KB each) ----
        const uint4* ga = (const uint4*)(gA + (ic << 5));
        const uint4* gw = (const uint4*)(gW + (ic << 5));
        #pragma unroll
        for (int c = 0; c < 4; c++) {
            int ch = lhalf + c;
            int so = sw0 + ((ch ^ swm) << 4);
            *(uint4*)(smA + so) = ga[ch];
            *(uint4*)(smB + so) = gw[ch];
        }
        __syncthreads();

        // ---- 4 x k8 MMA steps ----
        #pragma unroll
        for (int kk = 0; kk < 4; kk++) {
            u32 afr[4][4], bfr[2][4];
            #pragma unroll
            for (int mt = 0; mt < 4; mt++) {
                int row = wm + (mt << 4) + lr15;
                int ch  = ((kk << 1) + lc16) ^ (row & 7);
                LDMX4(afr[mt][0], afr[mt][1], afr[mt][2], afr[mt][3],
                      abase + row * 128 + (ch << 4));
            }
            #pragma unroll
            for (int g = 0; g < 2; g++) {
                int row = wn + (g << 4) + lr15;
                int ch  = ((kk << 1) + lc16) ^ (row & 7);
                LDMX4(bfr[g][0], bfr[g][1], bfr[g][2], bfr[g][3],
                      bbase + row * 128 + (ch << 4));
            }
            #pragma unroll
            for (int mt = 0; mt < 4; mt++)
                #pragma unroll
                for (int nt = 0; nt < 4; nt++) {
                    int g = nt >> 1, sub = nt & 1;
                    MMATF(acc[mt][nt], afr[mt], bfr[g][sub], bfr[g][2 + sub]);
                }
        }
        __syncthreads();
    }

    // ---- epilogue: fp32 store (+bias on slice 0) ----
    const int er = lane >> 2;                 // 0..7
    const int ec = (lane & 3) << 1;           // 0,2,4,6
    #pragma unroll
    for (int mt = 0; mt < 4; mt++) {
        int row0 = bm + wm + (mt << 4) + er;
        #pragma unroll
        for (int nt = 0; nt < 4; nt++) {
            int col = bn + wn + (nt << 3) + ec;
            float b0 = 0.f, b1 = 0.f;
            if (z == 0) { b0 = bias[col]; b1 = bias[col + 1]; }
            *(float2*)(C + (size_t)row0 * N + col) =
                make_float2(acc[mt][nt][0] + b0, acc[mt][nt][1] + b1);
            *(float2*)(C + (size_t)(row0 + 8) * N + col) =
                make_float2(acc[mt][nt][2] + b0, acc[mt][nt][3] + b1);
        }
    }
}

// ---------------- tf32 limb splits ----------------
// wmode 0 (A-side): [hi|hi|lo]; wmode 1 (W-side): [hi|lo|hi]
__global__ void split3t(const float* __restrict__ src, int lds,
                        float* __restrict__ dst, int R, int C, int wmode)
{
    int i = blockIdx.x * 256 + threadIdx.x;
    if (i >= R * C) return;
    int r = i / C, c = i - r * C;
    float a  = src[(size_t)r * lds + c];
    float hi = tf32f(a);
    float lo = tf32f(a - hi);
    size_t rb = (size_t)r * 3 * C;
    dst[rb + c]       = hi;
    dst[rb + C + c]   = wmode ? lo : hi;
    dst[rb + 2*C + c] = wmode ? hi : lo;
}

// A-side limb store for activations: [hi|hi|lo]
__device__ __forceinline__ void split4t(float* rowb, int Cc, int u, float4 v) {
    float4 hi, lo;
    hi.x = tf32f(v.x); lo.x = tf32f(v.x - hi.x);
    hi.y = tf32f(v.y); lo.y = tf32f(v.y - hi.y);
    hi.z = tf32f(v.z); lo.z = tf32f(v.z - hi.z);
    hi.w = tf32f(v.w); lo.w = tf32f(v.w - hi.w);
    *(float4*)(rowb + u)        = hi;
    *(float4*)(rowb + Cc + u)   = hi;
    *(float4*)(rowb + 2*Cc + u) = lo;
}

// ---------------- encoder GRU gate (writes h, ht limbs, enc_out, eot limbs) ------
__global__ void enc_gate(const float* __restrict__ gi, const float* __restrict__ ghp,
                         float* __restrict__ h, float* __restrict__ ht,
                         float* __restrict__ enc_out_t, float* __restrict__ eot_t,
                         const int* __restrict__ x_len, int t)
{
    int i = blockIdx.x * blockDim.x + threadIdx.x;       // float4 index
    int b = i >> 8;
    if (t >= x_len[b]) return;
    int u = (i & 255) << 2;
    size_t base = (size_t)b * G3U + u;
    const size_t MN = (size_t)Bz * G3U;
    float4 gr = *(const float4*)(ghp + base);
    float4 gz = *(const float4*)(ghp + base + UU);
    float4 gn = *(const float4*)(ghp + base + 2*UU);
    #pragma unroll
    for (int s = 1; s < GHKS; s++) {
        float4 a = *(const float4*)(ghp + s*MN + base);
        float4 c = *(const float4*)(ghp + s*MN + base + UU);
        float4 d = *(const float4*)(ghp + s*MN + base + 2*UU);
        gr.x+=a.x; gr.y+=a.y; gr.z+=a.z; gr.w+=a.w;
        gz.x+=c.x; gz.y+=c.y; gz.z+=c.z; gz.w+=c.w;
        gn.x+=d.x; gn.y+=d.y; gn.z+=d.z; gn.w+=d.w;
    }
    float4 ir = *(const float4*)(gi + base);
    float4 iz = *(const float4*)(gi + base + UU);
    float4 in = *(const float4*)(gi + base + 2*UU);
    float4 hv = *(const float4*)(h + (size_t)b*UU + u);
    float4 hn;
    {
        float r, z, n;
        r = fsigm(ir.x+gr.x); z = fsigm(iz.x+gz.x); n = ftanh(in.x + r*gn.x); hn.x = (1.f-z)*n + z*hv.x;
        r = fsigm(ir.y+gr.y); z = fsigm(iz.y+gz.y); n = ftanh(in.y + r*gn.y); hn.y = (1.f-z)*n + z*hv.y;
        r = fsigm(ir.z+gr.z); z = fsigm(iz.z+gz.z); n = ftanh(in.z + r*gn.z); hn.z = (1.f-z)*n + z*hv.z;
        r = fsigm(ir.w+gr.w); z = fsigm(iz.w+gz.w); n = ftanh(in.w + r*gn.w); hn.w = (1.f-z)*n + z*hv.w;
    }
    *(float4*)(h + (size_t)b*UU + u)         = hn;
    *(float4*)(enc_out_t + (size_t)b*UU + u) = hn;
    split4t(ht    + (size_t)b*KT_U, UU, u, hn);
    split4t(eot_t + (size_t)b*KT_U, UU, u, hn);
}

// ---------------- decoder GRU gate (writes h + ht limbs) ----------------
__global__ void dec_gate(const float* __restrict__ gip, const float* __restrict__ qghp,
                         const float* __restrict__ T, const int* __restrict__ idx,
                         float* __restrict__ h, float* __restrict__ ht)
{
    int i = blockIdx.x * blockDim.x + threadIdx.x;
    int b = i >> 8;
    int u = (i & 255) << 2;
    size_t gbase = (size_t)b * G3U + u;
    const size_t MN3 = (size_t)Bz * G3U;
    const float* tb = T + (size_t)idx[b] * G3U + u;
    float4 ir = *(const float4*)(tb);
    float4 iz = *(const float4*)(tb + UU);
    float4 in = *(const float4*)(tb + 2*UU);
    #pragma unroll
    for (int s = 0; s < GIKS; s++) {
        float4 a = *(const float4*)(gip + s*MN3 + gbase);
        float4 c = *(const float4*)(gip + s*MN3 + gbase + UU);
        float4 d = *(const float4*)(gip + s*MN3 + gbase + 2*UU);
        ir.x+=a.x; ir.y+=a.y; ir.z+=a.z; ir.w+=a.w;
        iz.x+=c.x; iz.y+=c.y; iz.z+=c.z; iz.w+=c.w;
        in.x+=d.x; in.y+=d.y; in.z+=d.z; in.w+=d.w;
    }
    size_t qbase = (size_t)b * NQP + u;
    const size_t MNq = (size_t)Bz * NQP;
    float4 gr = make_float4(0,0,0,0), gz = gr, gn = gr;
    #pragma unroll
    for (int s = 0; s < QGHKS; s++) {
        float4 a = *(const float4*)(qghp + s*MNq + qbase);
        float4 c = *(const float4*)(qghp + s*MNq + qbase + UU);
        float4 d = *(const float4*)(qghp + s*MNq + qbase + 2*UU);
        gr.x+=a.x; gr.y+=a.y; gr.z+=a.z; gr.w+=a.w;
        gz.x+=c.x; gz.y+=c.y; gz.z+=c.z; gz.w+=c.w;
        gn.x+=d.x; gn.y+=d.y; gn.z+=d.z; gn.w+=d.w;
    }
    float4 hv = *(const float4*)(h + (size_t)b*UU + u);
    float4 hn;
    {
        float r, z, n;
        r = fsigm(ir.x+gr.x); z = fsigm(iz.x+gz.x); n = ftanh(in.x + r*gn.x); hn.x = (1.f-z)*n + z*hv.x;
        r = fsigm(ir.y+gr.y); z = fsigm(iz.y+gz.y); n = ftanh(in.y + r*gn.y); hn.y = (1.f-z)*n + z*hv.y;
        r = fsigm(ir.z+gr.z); z = fsigm(iz.z+gz.z); n = ftanh(in.z + r*gn.z); hn.z = (1.f-z)*n + z*hv.z;
        r = fsigm(ir.w+gr.w); z = fsigm(iz.w+gz.w); n = ftanh(in.w + r*gn.w); hn.w = (1.f-z)*n + z*hv.w;
    }
    *(float4*)(h + (size_t)b*UU + u) = hn;
    split4t(ht + (size_t)b*KT_U, UU, u, hn);
}

// ------- fused attention (+ pred/argmax of prev step); writes ctx limbs ---------
__global__ void __launch_bounds__(256) fused_attn(
    const float* __restrict__ qghp, const float* __restrict__ enc_proj,
    const float* __restrict__ enc_out,
    const float* __restrict__ V_W, const float* __restrict__ V_b,
    const float* __restrict__ W1_b, const int* __restrict__ x_len,
    float* __restrict__ ctxt,
    float* __restrict__ out_t, int* __restrict__ idx)
{
    __shared__ float qs[UU];
    __shared__ float vs[UU];
    __shared__ float wb[UU];
    __shared__ float lg[Sn];
    __shared__ float sv[VOUTn];
    __shared__ int   si[VOUTn];
    const int b = blockIdx.x, tid = threadIdx.x;
    const int w = tid >> 5, lane = tid & 31;
    const size_t MNq = (size_t)Bz * NQP;
    const size_t qoff = (size_t)b * NQP + 3*UU;

    if (out_t) {
        if (tid < VOUTn) {
            size_t base = (size_t)b * NQP + 4096 + tid;
            float v = 0.f;
            #pragma unroll
            for (int s = 0; s < QGHKS; s++) v += qghp[s*MNq + base];
            out_t[(size_t)b * VOUTn + tid] = v;
            sv[tid] = v; si[tid] = tid;
        }
        __syncthreads();
        #pragma unroll
        for (int off = 64; off; off >>= 1) {
            if (tid < off) {
                float v2 = sv[tid+off]; int i2 = si[tid+off];
                if (v2 > sv[tid] || (v2 == sv[tid] && i2 < si[tid])) { sv[tid] = v2; si[tid] = i2; }
            }
            __syncthreads();
        }
        if (tid == 0) idx[b] = si[0];
    }

    #pragma unroll
    for (int k = 0; k < 4; k++) {
        int u = tid + 256*k;
        float qv = 0.f;
        #pragma unroll
        for (int s = 0; s < QGHKS; s++) qv += qghp[s*MNq + qoff + u];
        qs[u] = qv;
        vs[u] = V_W[u];
        wb[u] = W1_b[u];
    }
    __syncthreads();

    const int L = x_len[b];
    for (int s = w; s < L; s += 8) {
        const float4* ep = (const float4*)(enc_proj + ((size_t)s * Bz + b) * UU);
        const float4* q4 = (const float4*)qs;
        const float4* v4 = (const float4*)vs;
        float sum = 0.f;
        #pragma unroll
        for (int it = 0; it < 8; it++) {
            int u = lane + 32*it;
            float4 e = ep[u], qq = q4[u], vv = v4[u];
            sum += ftanh(e.x + qq.x) * vv.x + ftanh(e.y + qq.y) * vv.y
                 + ftanh(e.z + qq.z) * vv.z + ftanh(e.w + qq.w) * vv.w;
        }
        #pragma unroll
        for (int off = 16; off; off >>= 1)
            sum += __shfl_down_sync(0xffffffffu, sum, off);
        if (lane == 0) lg[s] = sum + V_b[0];
    }
    if (w == 0 && L < Sn) {          // masked s: enc_proj row == W1_b analytically
        const float4* q4 = (const float4*)qs;
        const float4* v4 = (const float4*)vs;
        const float4* w4 = (const float4*)wb;
        float sum = 0.f;
        #pragma unroll
        for (int it = 0; it < 8; it++) {
            int u = lane + 32*it;
            float4 e = w4[u], qq = q4[u], vv = v4[u];
            sum += ftanh(e.x + qq.x) * vv.x + ftanh(e.y + qq.y) * vv.y
                 + ftanh(e.z + qq.z) * vv.z + ftanh(e.w + qq.w) * vv.w;
        }
        #pragma unroll
        for (int off = 16; off; off >>= 1)
            sum += __shfl_down_sync(0xffffffffu, sum, off);
        if (lane == 0) {
            float c = sum + V_b[0];
            for (int s = L; s < Sn; s++) lg[s] = c;
        }
    }
    __syncthreads();

    if (w == 0) {
        float v0 = lg[lane], v1 = lg[lane + 32];
        float mx = fmaxf(v0, v1);
        #pragma unroll
        for (int off = 16; off; off >>= 1)
            mx = fmaxf(mx, __shfl_xor_sync(0xffffffffu, mx, off));
        float e0 = f_ex2(1.4426950408889634f * (v0 - mx));
        float e1 = f_ex2(1.4426950408889634f * (v1 - mx));
        float smv = e0 + e1;
        #pragma unroll
        for (int off = 16; off; off >>= 1)
            smv += __shfl_xor_sync(0xffffffffu, smv, off);
        float inv = f_rcp(smv);
        lg[lane]      = e0 * inv;
        lg[lane + 32] = e1 * inv;
    }
    __syncthreads();

    float4 c4 = make_float4(0,0,0,0);
    const int u = tid << 2;
    for (int s = 0; s < L; s++) {
        float a = lg[s];
        float4 eo = *(const float4*)(enc_out + ((size_t)s * Bz + b) * UU + u);
        c4.x += a * eo.x; c4.y += a * eo.y; c4.z += a * eo.z; c4.w += a * eo.w;
    }
    split4t(ctxt + (size_t)b * KT_U, UU, u, c4);
}

// ---------------- final pred: sum partials + write + argmax ----------------
__global__ void pred_argmax(const float* __restrict__ qghp,
                            float* __restrict__ out_t, int* __restrict__ idx)
{
    int b = blockIdx.x;
    int t = threadIdx.x;            // 128 threads
    const size_t MNq = (size_t)Bz * NQP;
    size_t base = (size_t)b * NQP + 4096 + t;
    float v = 0.f;
    #pragma unroll
    for (int s = 0; s < QGHKS; s++) v += qghp[s*MNq + base];
    out_t[(size_t)b * VOUTn + t] = v;

    __shared__ float sv[VOUTn];
    __shared__ int   si[VOUTn];
    sv[t] = v; si[t] = t;
    __syncthreads();
    #pragma unroll
    for (int off = 64; off; off >>= 1) {
        if (t < off) {
            float v2 = sv[t+off]; int i2 = si[t+off];
            if (v2 > sv[t] || (v2 == sv[t] && i2 < si[t])) { sv[t] = v2; si[t] = i2; }
        }
        __syncthreads();
    }
    if (t == 0) idx[b] = si[0];
}

// ---------------- one-time prep & init ----------------
__global__ void prep(const float* __restrict__ dec_Whh, const float* __restrict__ W2_W,
                     const float* __restrict__ fc_W,
                     const float* __restrict__ dec_bhh, const float* __restrict__ W2_b,
                     const float* __restrict__ fc_b,
                     const float* __restrict__ o2h_W,   const float* __restrict__ o2h_b,
                     float* __restrict__ Wqgh, float* __restrict__ bqgh,
                     float* __restrict__ Aemb)
{
    int i = blockIdx.x * 256 + threadIdx.x;          // 0 .. NQP*UU-1
    float wv;
    if (i < G3U*UU)            wv = dec_Whh[i];
    else if (i < (G3U+UU)*UU)  wv = W2_W[i - G3U*UU];
    else                       wv = fc_W[i - (G3U+UU)*UU];
    Wqgh[i] = wv;
    if (i < NQP) {
        float bv;
        if (i < G3U)           bv = dec_bhh[i];
        else if (i < G3U+UU)   bv = W2_b[i - G3U];
        else                   bv = fc_b[i - G3U - UU];
        bqgh[i] = bv;
    }
    if (i < VOUTn*EE) {
        int v = i / EE, e = i % EE;
        Aemb[i] = o2h_W[(size_t)e * VOUTn + v] + o2h_b[e];
    }
}

__global__ void init_all(float4* __restrict__ enc_out, float4* __restrict__ eot,
                         float4* __restrict__ h, float4* __restrict__ ht,
                         float4* __restrict__ out0, int* __restrict__ idx)
{
    size_t i = (size_t)blockIdx.x * 256 + threadIdx.x;   // over S*B*KT_U/4 float4s
    float4 zz = make_float4(0,0,0,0);
    eot[i] = zz;
    if (i < (size_t)Sn*Bz*UU/4) enc_out[i] = zz;
    if (i < Bz*UU/4)            h[i] = zz;
    if (i < Bz*KT_U/4)          ht[i] = zz;
    if (i < Bz*VOUTn/4)         out0[i] = ((i & 31) == 0) ? make_float4(1,0,0,0) : zz;
    if (i < Bz)                 idx[i] = 0;
}

// ---------------- driver ----------------
extern "C" void kernel_launch(void* const* d_in, const int* in_sizes, int n_in,
                              void* d_out, int out_size)
{
    const float* x       = (const float*)d_in[0];
    const int*   x_len   = (const int*)  d_in[1];
    const float* enc_Wih = (const float*)d_in[2];
    const float* enc_Whh = (const float*)d_in[3];
    const float* enc_bih = (const float*)d_in[4];
    const float* enc_bhh = (const float*)d_in[5];
    const float* dec_Wih = (const float*)d_in[6];
    const float* dec_Whh = (const float*)d_in[7];
    const float* dec_bih = (const float*)d_in[8];
    const float* dec_bhh = (const float*)d_in[9];
    const float* o2h_W   = (const float*)d_in[10];
    const float* o2h_b   = (const float*)d_in[11];
    const float* fc_W    = (const float*)d_in[12];
    const float* fc_b    = (const float*)d_in[13];
    const float* W1_W    = (const float*)d_in[14];
    const float* W1_b    = (const float*)d_in[15];
    const float* W2_W    = (const float*)d_in[16];
    const float* W2_b    = (const float*)d_in[17];
    const float* V_W     = (const float*)d_in[18];
    const float* V_b     = (const float*)d_in[19];
    float* out = (float*)d_out;

    float *gi_enc, *enc_out, *enc_proj, *h, *ghp, *gip, *qghp;
    float *Wqgh, *bqgh, *T, *Aemb, *zerob;
    float *xt, *Wiht, *Whht, *Wqght, *Wdct, *Wdet, *W1t, *Aembt, *ht, *eot, *ctxt;
    int* idx;
    cudaGetSymbolAddress((void**)&gi_enc,   g_gi_enc);
    cudaGetSymbolAddress((void**)&enc_out,  g_enc_out);
    cudaGetSymbolAddress((void**)&enc_proj, g_enc_proj);
    cudaGetSymbolAddress((void**)&h,        g_h);
    cudaGetSymbolAddress((void**)&ghp,      g_ghp);
    cudaGetSymbolAddress((void**)&gip,      g_gip);
    cudaGetSymbolAddress((void**)&qghp,     g_qghp);
    cudaGetSymbolAddress((void**)&idx,      g_idx);
    cudaGetSymbolAddress((void**)&Wqgh,     g_Wqgh);
    cudaGetSymbolAddress((void**)&bqgh,     g_bqgh);
    cudaGetSymbolAddress((void**)&T,        g_T);
    cudaGetSymbolAddress((void**)&Aemb,     g_Aemb);
    cudaGetSymbolAddress((void**)&zerob,    g_zero);
    cudaGetSymbolAddress((void**)&xt,       g_xt);
    cudaGetSymbolAddress((void**)&Wiht,     g_Wiht);
    cudaGetSymbolAddress((void**)&Whht,     g_Whht);
    cudaGetSymbolAddress((void**)&Wqght,    g_Wqght);
    cudaGetSymbolAddress((void**)&Wdct,     g_Wdct);
    cudaGetSymbolAddress((void**)&Wdet,     g_Wdet);
    cudaGetSymbolAddress((void**)&W1t,      g_W1t);
    cudaGetSymbolAddress((void**)&Aembt,    g_Aembt);
    cudaGetSymbolAddress((void**)&ht,       g_ht);
    cudaGetSymbolAddress((void**)&eot,      g_eot);
    cudaGetSymbolAddress((void**)&ctxt,     g_ctxt);

    // ---- one-time prep: fp32 concat + tf32 limb-pair splits ----
    prep<<<(NQP*UU)/256, 256>>>(dec_Whh, W2_W, fc_W, dec_bhh, W2_b, fc_b,
                                o2h_W, o2h_b, Wqgh, bqgh, Aemb);
    split3t<<<(Sn*Bz*VIN)/256, 256>>>(x,       VIN,   xt,    Sn*Bz, VIN, 0);
    split3t<<<(G3U*VIN)/256, 256>>>(enc_Wih,   VIN,   Wiht,  G3U,   VIN, 1);
    split3t<<<(G3U*UU)/256, 256>>>(enc_Whh,    UU,    Whht,  G3U,   UU,  1);
    split3t<<<(NQP*UU)/256, 256>>>(Wqgh,       UU,    Wqght, NQP,   UU,  1);
    split3t<<<(G3U*UU)/256, 256>>>(dec_Wih,    UU+EE, Wdct,  G3U,   UU,  1);
    split3t<<<(G3U*EE)/256, 256>>>(dec_Wih+UU, UU+EE, Wdet,  G3U,   EE,  1);
    split3t<<<(UU*UU)/256, 256>>>(W1_W,        UU,    W1t,   UU,    UU,  1);
    split3t<<<(VOUTn*EE)/256, 256>>>(Aemb,     EE,    Aembt, VOUTn, EE,  0);
    init_all<<<(int)(((size_t)Sn*Bz*KT_U/4)/256), 256>>>(
        (float4*)enc_out, (float4*)eot, (float4*)h, (float4*)ht, (float4*)out, idx);

    // emb->gi table: T[128,3U] = Aemb @ dec_Wih_emb^T + dec_bih
    gemmt<<<dim3(G3U/128, 1, 1), 256>>>(Aembt, Wdet, dec_bih, T,
                                        VOUTn, G3U, KT_E, 1, nullptr, -1);
    // encoder input gates, all steps (skip fully-masked 128-row tiles)
    gemmt<<<dim3(G3U/128, (Sn*Bz)/128, 1), 256>>>(xt, Wiht, enc_bih, gi_enc,
                                        Sn*Bz, G3U, KT_VIN, 1, x_len, -1);

    // ---- Encoder: 64 sequential GRU steps (active-suffix only) ----
    for (int t = 0; t < Sn; t++) {
        gemmt<<<dim3(G3U/128, Bz/128, GHKS), 256>>>(ht, Whht, enc_bhh, ghp,
                                        Bz, G3U, KT_U, GHKS, x_len, t);
        enc_gate<<<(Bz*UU/4)/256, 256>>>(gi_enc + (size_t)t*Bz*G3U, ghp, h, ht,
                                         enc_out + (size_t)t*Bz*UU,
                                         eot + (size_t)t*Bz*KT_U, x_len, t);
    }

    // enc_proj = enc_out @ W1^T + b
    gemmt<<<dim3(UU/128, (Sn*Bz)/128, 1), 256>>>(eot, W1t, W1_b, enc_proj,
                                        Sn*Bz, UU, KT_U, 1, x_len, -1);

    // ---- Decoder: 24 steps; [gh|q|pred] one GEMM; pred_{k-1} fused into attn ----
    for (int k = 1; k <= TDEC - 1; k++) {
        gemmt<<<dim3(NQP/128, Bz/128, QGHKS), 256>>>(ht, Wqght, bqgh, qghp,
                                        Bz, NQP, KT_U, QGHKS, nullptr, -1);
        fused_attn<<<Bz, 256>>>(qghp, enc_proj, enc_out, V_W, V_b, W1_b,
                                x_len, ctxt,
                                (k >= 2) ? out + (size_t)(k-1)*Bz*VOUTn : nullptr,
                                idx);
        gemmt<<<dim3(G3U/128, Bz/128, GIKS), 256>>>(ctxt, Wdct, zerob, gip,
                                        Bz, G3U, KT_U, GIKS, nullptr, -1);
        dec_gate<<<(Bz*UU/4)/256, 256>>>(gip, qghp, T, idx, h, ht);
    }
    // final pred: fc(h_24) = out[24]
    gemmt<<<dim3(NQP/128, Bz/128, QGHKS), 256>>>(ht, Wqght, bqgh, qghp,
                                        Bz, NQP, KT_U, QGHKS, nullptr, -1);
    pred_argmax<<<Bz, 128>>>(qghp, out + (size_t)(TDEC-1)*Bz*VOUTn, idx);
}

// round 16
// speedup vs baseline: 1.1273x; 1.1273x over previous
#include <cuda_runtime.h>
#include <math.h>

typedef unsigned long long ull;
typedef unsigned int u32;

#define Sn    64
#define Bz    256
#define VIN   128
#define VOUTn 128
#define UU    1024
#define EE    512
#define TDEC  25
#define G3U   3072
#define NQP   4224            // [gh(3072) | q(1024) | pred(128)]
#define GHKS  3
#define GIKS  3
#define QGHKS 2
#define KL_U   (2*UU)         // tf32 limb storage [hi|lo] along K
#define KL_VIN (2*VIN)
#define KL_E   (2*EE)
#define GSMEM  131072         // 2 stages x 4 tiles x 16KB

// ---------------- fp32 scratch ----------------
__device__ __align__(16) float g_gi_enc[(size_t)Sn*Bz*G3U];
__device__ __align__(16) float g_enc_out[(size_t)Sn*Bz*UU];
__device__ __align__(16) float g_enc_proj[(size_t)Sn*Bz*UU];
__device__ __align__(16) float g_h[Bz*UU];
__device__ __align__(16) float g_ghp[(size_t)GHKS*Bz*G3U];
__device__ __align__(16) float g_gip[(size_t)GIKS*Bz*G3U];
__device__ __align__(16) float g_qghp[(size_t)QGHKS*Bz*NQP];
__device__ int   g_idx[Bz];
__device__ __align__(16) float g_Wqgh[(size_t)NQP*UU];
__device__ __align__(16) float g_bqgh[NQP];
__device__ __align__(16) float g_T[(size_t)VOUTn*G3U];
__device__ __align__(16) float g_Aemb[VOUTn*EE];
__device__ __align__(16) float g_zero[NQP];

// ---------------- tf32 limb scratch ([hi|lo] concatenated along K) --------------
__device__ __align__(16) float g_xt   [(size_t)Sn*Bz*KL_VIN];
__device__ __align__(16) float g_Wiht [(size_t)G3U*KL_VIN];
__device__ __align__(16) float g_Whht [(size_t)G3U*KL_U];
__device__ __align__(16) float g_Wqght[(size_t)NQP*KL_U];
__device__ __align__(16) float g_Wdct [(size_t)G3U*KL_U];
__device__ __align__(16) float g_Wdet [(size_t)G3U*KL_E];
__device__ __align__(16) float g_W1t  [(size_t)UU*KL_U];
__device__ __align__(16) float g_Aembt[(size_t)VOUTn*KL_E];
__device__ __align__(16) float g_ht   [(size_t)Bz*KL_U];
__device__ __align__(16) float g_eot  [(size_t)Sn*Bz*KL_U];
__device__ __align__(16) float g_ctxt [(size_t)Bz*KL_U];

// ---------------- fast (~1e-7) transcendentals ----------------
__device__ __forceinline__ float f_ex2(float x){ float r; asm("ex2.approx.f32 %0, %1;" : "=f"(r) : "f"(x)); return r; }
__device__ __forceinline__ float f_rcp(float x){ float r; asm("rcp.approx.f32 %0, %1;" : "=f"(r) : "f"(x)); return r; }
__device__ __forceinline__ float fsigm(float x){ return f_rcp(1.f + f_ex2(-1.4426950408889634f*x)); }
__device__ __forceinline__ float ftanh(float x){ return 1.f - 2.f*f_rcp(1.f + f_ex2(2.8853900817779268f*x)); }

__device__ __forceinline__ float tf32f(float a) {
    u32 u; asm("cvt.rna.tf32.f32 %0, %1;" : "=r"(u) : "f"(a));
    return __uint_as_float(u);
}
__device__ __forceinline__ u32 s2u(const void* p) {
    u32 a; asm("{ .reg .u64 t; cvta.to.shared.u64 t, %1; cvt.u32.u64 %0, t; }" : "=r"(a) : "l"(p));
    return a;
}
__device__ __forceinline__ void cpa16(u32 dst, const void* src) {
    asm volatile("cp.async.cg.shared.global [%0], [%1], 16;" :: "r"(dst), "l"(src));
}
#define CP_COMMIT() asm volatile("cp.async.commit_group;" ::: "memory")
#define CP_WAIT1()  asm volatile("cp.async.wait_group 1;" ::: "memory")
#define CP_WAIT0()  asm volatile("cp.async.wait_group 0;" ::: "memory")

#define LDMX4(r0, r1, r2, r3, addr) \
    asm volatile("ldmatrix.sync.aligned.m8n8.x4.shared.b16 {%0,%1,%2,%3}, [%4];" \
        : "=r"(r0), "=r"(r1), "=r"(r2), "=r"(r3) : "r"(addr))

#define MMATF(d, a, b0, b1) \
    asm volatile("mma.sync.aligned.m16n8k8.row.col.f32.tf32.tf32.f32 " \
        "{%0,%1,%2,%3}, {%4,%5,%6,%7}, {%8,%9}, {%0,%1,%2,%3};" \
        : "+f"((d)[0]), "+f"((d)[1]), "+f"((d)[2]), "+f"((d)[3]) \
        : "r"((a)[0]), "r"((a)[1]), "r"((a)[2]), "r"((a)[3]), "r"(b0), "r"(b1))

// ------- tf32 limb GEMM: C[M,N] = A@W^T in full fp32-grade precision -------------
// A, W stored as [hi|lo] limbs along K (row stride 2K). Per 32-k window, stage
// A_hi/A_lo/W_hi/W_lo tiles (cp.async, 2-stage pipeline) and accumulate the 3
// products hi*hi + hi*lo + lo*hi (lo*lo ~2^-22, dropped).
// 128x128 tile/CTA, 256 thr (8 warps 2x4), warp 64x32, m16n8k8 tf32, fp32 acc.
// grid=(N/128, M/128, KS); slice z -> C + z*M*N over its window range.
// sorted-x_len early exit: tstep>=0: rows=batch; tstep<0: rows=s*256+b.
__global__ void __launch_bounds__(256) gemmt(
    const float* __restrict__ A, const float* __restrict__ W,
    const float* __restrict__ bias, float* __restrict__ C,
    int M, int N, int K, int KS,
    const int* __restrict__ x_len, int tstep)
{
    const int bm = blockIdx.y * 128;
    if (x_len) {
        int t_eff = (tstep >= 0) ? tstep : (bm >> 8);
        int b_hi  = (tstep >= 0) ? (bm + 127) : ((bm & 255) + 127);
        if (x_len[b_hi] <= t_eff) return;
    }
    extern __shared__ __align__(16) char sm[];
    const u32 sb = s2u(sm);

    const int tid  = threadIdx.x;
    const int wid  = tid >> 5;
    const int lane = tid & 31;
    const int wm   = (wid >> 2) << 6;        // 0 / 64
    const int wn   = (wid & 3) << 5;         // 0..96
    const int bn   = blockIdx.x * 128;

    const int z  = blockIdx.z;
    const int NW = K >> 5;                   // 32-k windows
    const int w0 = (NW * z) / KS, w1 = (NW * (z + 1)) / KS;
    C += (size_t)z * M * N;

    float acc[4][4][4];
    #pragma unroll
    for (int i = 0; i < 4; i++)
        #pragma unroll
        for (int j = 0; j < 4; j++)
            #pragma unroll
            for (int r = 0; r < 4; r++) acc[i][j][r] = 0.f;

    const int lrow  = tid >> 1;               // 0..127
    const int lhalf = (tid & 1) << 2;         // chunk 0 or 4
    const int lr15  = lane & 15;
    const int lc16  = lane >> 4;              // 0/1
    const int sw0   = lrow * 128;
    const int swm   = lrow & 7;

    const float* gAr = A + (size_t)(bm + lrow) * (2 * K);
    const float* gWr = W + (size_t)(bn + lrow) * (2 * K);

    // stage window w into pipeline stage s (4 tiles: A_hi, A_lo, W_hi, W_lo)
    auto stage = [&](int s, int w) {
        const u32 base = sb + s * 65536;
        const float* srcs[4] = { gAr + (w << 5), gAr + K + (w << 5),
                                 gWr + (w << 5), gWr + K + (w << 5) };
        #pragma unroll
        for (int tI = 0; tI < 4; tI++) {
            const uint4* g = (const uint4*)srcs[tI];
            #pragma unroll
            for (int c = 0; c < 4; c++) {
                int ch = lhalf + c;
                int so = sw0 + ((ch ^ swm) << 4);
                cpa16(base + tI * 16384 + so, g + ch);
            }
        }
    };

    auto compute = [&](int s) {
        const u32 base = sb + s * 65536;
        #pragma unroll
        for (int kk = 0; kk < 4; kk++) {
            u32 bH[2][4], bL[2][4];
            #pragma unroll
            for (int g = 0; g < 2; g++) {
                int row = wn + (g << 4) + lr15;
                int ch  = ((kk << 1) + lc16) ^ (row & 7);
                u32 off = row * 128 + (ch << 4);
                LDMX4(bH[g][0], bH[g][1], bH[g][2], bH[g][3], base + 32768 + off);
                LDMX4(bL[g][0], bL[g][1], bL[g][2], bL[g][3], base + 49152 + off);
            }
            #pragma unroll
            for (int mt = 0; mt < 4; mt++) {
                int row = wm + (mt << 4) + lr15;
                int ch  = ((kk << 1) + lc16) ^ (row & 7);
                u32 off = row * 128 + (ch << 4);
                u32 aH[4], aL[4];
                LDMX4(aH[0], aH[1], aH[2], aH[3], base + off);
                LDMX4(aL[0], aL[1], aL[2], aL[3], base + 16384 + off);
                #pragma unroll
                for (int nt = 0; nt < 4; nt++) {
                    int g = nt >> 1, sub = nt & 1;
                    MMATF(acc[mt][nt], aH, bH[g][sub], bH[g][2 + sub]);
                    MMATF(acc[mt][nt], aH, bL[g][sub], bL[g][2 + sub]);
                    MMATF(acc[mt][nt], aL, bH[g][sub], bH[g][2 + sub]);
                }
            }
        }
    };

    const int nw = w1 - w0;
    stage(0, w0); CP_COMMIT();
    for (int i = 0; i < nw; i++) {
        if (i + 1 < nw) { stage((i + 1) & 1, w0 + i + 1); CP_COMMIT(); CP_WAIT1(); }
        else            { CP_WAIT0(); }
        __syncthreads();
        compute(i & 1);
        __syncthreads();
    }

    // ---- epilogue: fp32 store (+bias on slice 0) ----
    const int er = lane >> 2;                 // 0..7
    const int ec = (lane & 3) << 1;           // 0,2,4,6
    #pragma unroll
    for (int mt = 0; mt < 4; mt++) {
        int row0 = bm + wm + (mt << 4) + er;
        #pragma unroll
        for (int nt = 0; nt < 4; nt++) {
            int col = bn + wn + (nt << 3) + ec;
            float b0 = 0.f, b1 = 0.f;
            if (z == 0) { b0 = bias[col]; b1 = bias[col + 1]; }
            *(float2*)(C + (size_t)row0 * N + col) =
                make_float2(acc[mt][nt][0] + b0, acc[mt][nt][1] + b1);
            *(float2*)(C + (size_t)(row0 + 8) * N + col) =
                make_float2(acc[mt][nt][2] + b0, acc[mt][nt][3] + b1);
        }
    }
}

// ---------------- tf32 limb splits ([hi|lo]) ----------------
__global__ void split2(const float* __restrict__ src, int lds,
                       float* __restrict__ dst, int R, int C)
{
    int i = blockIdx.x * 256 + threadIdx.x;
    if (i >= R * C) return;
    int r = i / C, c = i - r * C;
    float a  = src[(size_t)r * lds + c];
    float hi = tf32f(a);
    float lo = tf32f(a - hi);
    size_t rb = (size_t)r * 2 * C;
    dst[rb + c] = hi; dst[rb + C + c] = lo;
}

__device__ __forceinline__ void split4l(float* rowb, int Kc, int u, float4 v) {
    float4 hi, lo;
    hi.x = tf32f(v.x); lo.x = tf32f(v.x - hi.x);
    hi.y = tf32f(v.y); lo.y = tf32f(v.y - hi.y);
    hi.z = tf32f(v.z); lo.z = tf32f(v.z - hi.z);
    hi.w = tf32f(v.w); lo.w = tf32f(v.w - hi.w);
    *(float4*)(rowb + u)      = hi;
    *(float4*)(rowb + Kc + u) = lo;
}

// ---------------- encoder GRU gate ----------------
__global__ void enc_gate(const float* __restrict__ gi, const float* __restrict__ ghp,
                         float* __restrict__ h, float* __restrict__ ht,
                         float* __restrict__ enc_out_t, float* __restrict__ eot_t,
                         const int* __restrict__ x_len, int t)
{
    int i = blockIdx.x * blockDim.x + threadIdx.x;       // float4 index
    int b = i >> 8;
    if (t >= x_len[b]) return;
    int u = (i & 255) << 2;
    size_t base = (size_t)b * G3U + u;
    const size_t MN = (size_t)Bz * G3U;
    float4 gr = *(const float4*)(ghp + base);
    float4 gz = *(const float4*)(ghp + base + UU);
    float4 gn = *(const float4*)(ghp + base + 2*UU);
    #pragma unroll
    for (int s = 1; s < GHKS; s++) {
        float4 a = *(const float4*)(ghp + s*MN + base);
        float4 c = *(const float4*)(ghp + s*MN + base + UU);
        float4 d = *(const float4*)(ghp + s*MN + base + 2*UU);
        gr.x+=a.x; gr.y+=a.y; gr.z+=a.z; gr.w+=a.w;
        gz.x+=c.x; gz.y+=c.y; gz.z+=c.z; gz.w+=c.w;
        gn.x+=d.x; gn.y+=d.y; gn.z+=d.z; gn.w+=d.w;
    }
    float4 ir = *(const float4*)(gi + base);
    float4 iz = *(const float4*)(gi + base + UU);
    float4 in = *(const float4*)(gi + base + 2*UU);
    float4 hv = *(const float4*)(h + (size_t)b*UU + u);
    float4 hn;
    {
        float r, z, n;
        r = fsigm(ir.x+gr.x); z = fsigm(iz.x+gz.x); n = ftanh(in.x + r*gn.x); hn.x = (1.f-z)*n + z*hv.x;
        r = fsigm(ir.y+gr.y); z = fsigm(iz.y+gz.y); n = ftanh(in.y + r*gn.y); hn.y = (1.f-z)*n + z*hv.y;
        r = fsigm(ir.z+gr.z); z = fsigm(iz.z+gz.z); n = ftanh(in.z + r*gn.z); hn.z = (1.f-z)*n + z*hv.z;
        r = fsigm(ir.w+gr.w); z = fsigm(iz.w+gz.w); n = ftanh(in.w + r*gn.w); hn.w = (1.f-z)*n + z*hv.w;
    }
    *(float4*)(h + (size_t)b*UU + u)         = hn;
    *(float4*)(enc_out_t + (size_t)b*UU + u) = hn;
    split4l(ht    + (size_t)b*KL_U, UU, u, hn);
    split4l(eot_t + (size_t)b*KL_U, UU, u, hn);
}

// ---------------- decoder GRU gate ----------------
__global__ void dec_gate(const float* __restrict__ gip, const float* __restrict__ qghp,
                         const float* __restrict__ T, const int* __restrict__ idx,
                         float* __restrict__ h, float* __restrict__ ht)
{
    int i = blockIdx.x * blockDim.x + threadIdx.x;
    int b = i >> 8;
    int u = (i & 255) << 2;
    size_t gbase = (size_t)b * G3U + u;
    const size_t MN3 = (size_t)Bz * G3U;
    const float* tb = T + (size_t)idx[b] * G3U + u;
    float4 ir = *(const float4*)(tb);
    float4 iz = *(const float4*)(tb + UU);
    float4 in = *(const float4*)(tb + 2*UU);
    #pragma unroll
    for (int s = 0; s < GIKS; s++) {
        float4 a = *(const float4*)(gip + s*MN3 + gbase);
        float4 c = *(const float4*)(gip + s*MN3 + gbase + UU);
        float4 d = *(const float4*)(gip + s*MN3 + gbase + 2*UU);
        ir.x+=a.x; ir.y+=a.y; ir.z+=a.z; ir.w+=a.w;
        iz.x+=c.x; iz.y+=c.y; iz.z+=c.z; iz.w+=c.w;
        in.x+=d.x; in.y+=d.y; in.z+=d.z; in.w+=d.w;
    }
    size_t qbase = (size_t)b * NQP + u;
    const size_t MNq = (size_t)Bz * NQP;
    float4 gr = make_float4(0,0,0,0), gz = gr, gn = gr;
    #pragma unroll
    for (int s = 0; s < QGHKS; s++) {
        float4 a = *(const float4*)(qghp + s*MNq + qbase);
        float4 c = *(const float4*)(qghp + s*MNq + qbase + UU);
        float4 d = *(const float4*)(qghp + s*MNq + qbase + 2*UU);
        gr.x+=a.x; gr.y+=a.y; gr.z+=a.z; gr.w+=a.w;
        gz.x+=c.x; gz.y+=c.y; gz.z+=c.z; gz.w+=c.w;
        gn.x+=d.x; gn.y+=d.y; gn.z+=d.z; gn.w+=d.w;
    }
    float4 hv = *(const float4*)(h + (size_t)b*UU + u);
    float4 hn;
    {
        float r, z, n;
        r = fsigm(ir.x+gr.x); z = fsigm(iz.x+gz.x); n = ftanh(in.x + r*gn.x); hn.x = (1.f-z)*n + z*hv.x;
        r = fsigm(ir.y+gr.y); z = fsigm(iz.y+gz.y); n = ftanh(in.y + r*gn.y); hn.y = (1.f-z)*n + z*hv.y;
        r = fsigm(ir.z+gr.z); z = fsigm(iz.z+gz.z); n = ftanh(in.z + r*gn.z); hn.z = (1.f-z)*n + z*hv.z;
        r = fsigm(ir.w+gr.w); z = fsigm(iz.w+gz.w); n = ftanh(in.w + r*gn.w); hn.w = (1.f-z)*n + z*hv.w;
    }
    *(float4*)(h + (size_t)b*UU + u) = hn;
    split4l(ht + (size_t)b*KL_U, UU, u, hn);
}

// ------- fused attention (+ pred/argmax of prev step); writes ctx limbs ---------
__global__ void __launch_bounds__(256) fused_attn(
    const float* __restrict__ qghp, const float* __restrict__ enc_proj,
    const float* __restrict__ enc_out,
    const float* __restrict__ V_W, const float* __restrict__ V_b,
    const float* __restrict__ W1_b, const int* __restrict__ x_len,
    float* __restrict__ ctxt,
    float* __restrict__ out_t, int* __restrict__ idx)
{
    __shared__ float qs[UU];
    __shared__ float vs[UU];
    __shared__ float wb[UU];
    __shared__ float lg[Sn];
    __shared__ float sv[VOUTn];
    __shared__ int   si[VOUTn];
    const int b = blockIdx.x, tid = threadIdx.x;
    const int w = tid >> 5, lane = tid & 31;
    const size_t MNq = (size_t)Bz * NQP;
    const size_t qoff = (size_t)b * NQP + 3*UU;

    if (out_t) {
        if (tid < VOUTn) {
            size_t base = (size_t)b * NQP + 4096 + tid;
            float v = 0.f;
            #pragma unroll
            for (int s = 0; s < QGHKS; s++) v += qghp[s*MNq + base];
            out_t[(size_t)b * VOUTn + tid] = v;
            sv[tid] = v; si[tid] = tid;
        }
        __syncthreads();
        #pragma unroll
        for (int off = 64; off; off >>= 1) {
            if (tid < off) {
                float v2 = sv[tid+off]; int i2 = si[tid+off];
                if (v2 > sv[tid] || (v2 == sv[tid] && i2 < si[tid])) { sv[tid] = v2; si[tid] = i2; }
            }
            __syncthreads();
        }
        if (tid == 0) idx[b] = si[0];
    }

    #pragma unroll
    for (int k = 0; k < 4; k++) {
        int u = tid + 256*k;
        float qv = 0.f;
        #pragma unroll
        for (int s = 0; s < QGHKS; s++) qv += qghp[s*MNq + qoff + u];
        qs[u] = qv;
        vs[u] = V_W[u];
        wb[u] = W1_b[u];
    }
    __syncthreads();

    const int L = x_len[b];
    for (int s = w; s < L; s += 8) {
        const float4* ep = (const float4*)(enc_proj + ((size_t)s * Bz + b) * UU);
        const float4* q4 = (const float4*)qs;
        const float4* v4 = (const float4*)vs;
        float sum = 0.f;
        #pragma unroll
        for (int it = 0; it < 8; it++) {
            int u = lane + 32*it;
            float4 e = ep[u], qq = q4[u], vv = v4[u];
            sum += ftanh(e.x + qq.x) * vv.x + ftanh(e.y + qq.y) * vv.y
                 + ftanh(e.z + qq.z) * vv.z + ftanh(e.w + qq.w) * vv.w;
        }
        #pragma unroll
        for (int off = 16; off; off >>= 1)
            sum += __shfl_down_sync(0xffffffffu, sum, off);
        if (lane == 0) lg[s] = sum + V_b[0];
    }
    if (w == 0 && L < Sn) {          // masked s: enc_proj row == W1_b analytically
        const float4* q4 = (const float4*)qs;
        const float4* v4 = (const float4*)vs;
        const float4* w4 = (const float4*)wb;
        float sum = 0.f;
        #pragma unroll
        for (int it = 0; it < 8; it++) {
            int u = lane + 32*it;
            float4 e = w4[u], qq = q4[u], vv = v4[u];
            sum += ftanh(e.x + qq.x) * vv.x + ftanh(e.y + qq.y) * vv.y
                 + ftanh(e.z + qq.z) * vv.z + ftanh(e.w + qq.w) * vv.w;
        }
        #pragma unroll
        for (int off = 16; off; off >>= 1)
            sum += __shfl_down_sync(0xffffffffu, sum, off);
        if (lane == 0) {
            float c = sum + V_b[0];
            for (int s = L; s < Sn; s++) lg[s] = c;
        }
    }
    __syncthreads();

    if (w == 0) {
        float v0 = lg[lane], v1 = lg[lane + 32];
        float mx = fmaxf(v0, v1);
        #pragma unroll
        for (int off = 16; off; off >>= 1)
            mx = fmaxf(mx, __shfl_xor_sync(0xffffffffu, mx, off));
        float e0 = f_ex2(1.4426950408889634f * (v0 - mx));
        float e1 = f_ex2(1.4426950408889634f * (v1 - mx));
        float smv = e0 + e1;
        #pragma unroll
        for (int off = 16; off; off >>= 1)
            smv += __shfl_xor_sync(0xffffffffu, smv, off);
        float inv = f_rcp(smv);
        lg[lane]      = e0 * inv;
        lg[lane + 32] = e1 * inv;
    }
    __syncthreads();

    float4 c4 = make_float4(0,0,0,0);
    const int u = tid << 2;
    for (int s = 0; s < L; s++) {
        float a = lg[s];
        float4 eo = *(const float4*)(enc_out + ((size_t)s * Bz + b) * UU + u);
        c4.x += a * eo.x; c4.y += a * eo.y; c4.z += a * eo.z; c4.w += a * eo.w;
    }
    split4l(ctxt + (size_t)b * KL_U, UU, u, c4);
}

// ---------------- final pred: sum partials + write + argmax ----------------
__global__ void pred_argmax(const float* __restrict__ qghp,
                            float* __restrict__ out_t, int* __restrict__ idx)
{
    int b = blockIdx.x;
    int t = threadIdx.x;            // 128 threads
    const size_t MNq = (size_t)Bz * NQP;
    size_t base = (size_t)b * NQP + 4096 + t;
    float v = 0.f;
    #pragma unroll
    for (int s = 0; s < QGHKS; s++) v += qghp[s*MNq + base];
    out_t[(size_t)b * VOUTn + t] = v;

    __shared__ float sv[VOUTn];
    __shared__ int   si[VOUTn];
    sv[t] = v; si[t] = t;
    __syncthreads();
    #pragma unroll
    for (int off = 64; off; off >>= 1) {
        if (t < off) {
            float v2 = sv[t+off]; int i2 = si[t+off];
            if (v2 > sv[t] || (v2 == sv[t] && i2 < si[t])) { sv[t] = v2; si[t] = i2; }
        }
        __syncthreads();
    }
    if (t == 0) idx[b] = si[0];
}

// ---------------- one-time prep & init ----------------
__global__ void prep(const float* __restrict__ dec_Whh, const float* __restrict__ W2_W,
                     const float* __restrict__ fc_W,
                     const float* __restrict__ dec_bhh, const float* __restrict__ W2_b,
                     const float* __restrict__ fc_b,
                     const float* __restrict__ o2h_W,   const float* __restrict__ o2h_b,
                     float* __restrict__ Wqgh, float* __restrict__ bqgh,
                     float* __restrict__ Aemb)
{
    int i = blockIdx.x * 256 + threadIdx.x;          // 0 .. NQP*UU-1
    float wv;
    if (i < G3U*UU)            wv = dec_Whh[i];
    else if (i < (G3U+UU)*UU)  wv = W2_W[i - G3U*UU];
    else                       wv = fc_W[i - (G3U+UU)*UU];
    Wqgh[i] = wv;
    if (i < NQP) {
        float bv;
        if (i < G3U)           bv = dec_bhh[i];
        else if (i < G3U+UU)   bv = W2_b[i - G3U];
        else                   bv = fc_b[i - G3U - UU];
        bqgh[i] = bv;
    }
    if (i < VOUTn*EE) {
        int v = i / EE, e = i % EE;
        Aemb[i] = o2h_W[(size_t)e * VOUTn + v] + o2h_b[e];
    }
}

__global__ void init_all(float4* __restrict__ enc_out, float4* __restrict__ eot,
                         float4* __restrict__ h, float4* __restrict__ ht,
                         float4* __restrict__ out0, int* __restrict__ idx)
{
    size_t i = (size_t)blockIdx.x * 256 + threadIdx.x;   // over S*B*KL_U/4 float4s
    float4 zz = make_float4(0,0,0,0);
    eot[i] = zz;
    if (i < (size_t)Sn*Bz*UU/4) enc_out[i] = zz;
    if (i < Bz*UU/4)            h[i] = zz;
    if (i < Bz*KL_U/4)          ht[i] = zz;
    if (i < Bz*VOUTn/4)         out0[i] = ((i & 31) == 0) ? make_float4(1,0,0,0) : zz;
    if (i < Bz)                 idx[i] = 0;
}

// ---------------- driver ----------------
extern "C" void kernel_launch(void* const* d_in, const int* in_sizes, int n_in,
                              void* d_out, int out_size)
{
    const float* x       = (const float*)d_in[0];
    const int*   x_len   = (const int*)  d_in[1];
    const float* enc_Wih = (const float*)d_in[2];
    const float* enc_Whh = (const float*)d_in[3];
    const float* enc_bih = (const float*)d_in[4];
    const float* enc_bhh = (const float*)d_in[5];
    const float* dec_Wih = (const float*)d_in[6];
    const float* dec_Whh = (const float*)d_in[7];
    const float* dec_bih = (const float*)d_in[8];
    const float* dec_bhh = (const float*)d_in[9];
    const float* o2h_W   = (const float*)d_in[10];
    const float* o2h_b   = (const float*)d_in[11];
    const float* fc_W    = (const float*)d_in[12];
    const float* fc_b    = (const float*)d_in[13];
    const float* W1_W    = (const float*)d_in[14];
    const float* W1_b    = (const float*)d_in[15];
    const float* W2_W    = (const float*)d_in[16];
    const float* W2_b    = (const float*)d_in[17];
    const float* V_W     = (const float*)d_in[18];
    const float* V_b     = (const float*)d_in[19];
    float* out = (float*)d_out;

    float *gi_enc, *enc_out, *enc_proj, *h, *ghp, *gip, *qghp;
    float *Wqgh, *bqgh, *T, *Aemb, *zerob;
    float *xt, *Wiht, *Whht, *Wqght, *Wdct, *Wdet, *W1t, *Aembt, *ht, *eot, *ctxt;
    int* idx;
    cudaGetSymbolAddress((void**)&gi_enc,   g_gi_enc);
    cudaGetSymbolAddress((void**)&enc_out,  g_enc_out);
    cudaGetSymbolAddress((void**)&enc_proj, g_enc_proj);
    cudaGetSymbolAddress((void**)&h,        g_h);
    cudaGetSymbolAddress((void**)&ghp,      g_ghp);
    cudaGetSymbolAddress((void**)&gip,      g_gip);
    cudaGetSymbolAddress((void**)&qghp,     g_qghp);
    cudaGetSymbolAddress((void**)&idx,      g_idx);
    cudaGetSymbolAddress((void**)&Wqgh,     g_Wqgh);
    cudaGetSymbolAddress((void**)&bqgh,     g_bqgh);
    cudaGetSymbolAddress((void**)&T,        g_T);
    cudaGetSymbolAddress((void**)&Aemb,     g_Aemb);
    cudaGetSymbolAddress((void**)&zerob,    g_zero);
    cudaGetSymbolAddress((void**)&xt,       g_xt);
    cudaGetSymbolAddress((void**)&Wiht,     g_Wiht);
    cudaGetSymbolAddress((void**)&Whht,     g_Whht);
    cudaGetSymbolAddress((void**)&Wqght,    g_Wqght);
    cudaGetSymbolAddress((void**)&Wdct,     g_Wdct);
    cudaGetSymbolAddress((void**)&Wdet,     g_Wdet);
    cudaGetSymbolAddress((void**)&W1t,      g_W1t);
    cudaGetSymbolAddress((void**)&Aembt,    g_Aembt);
    cudaGetSymbolAddress((void**)&ht,       g_ht);
    cudaGetSymbolAddress((void**)&eot,      g_eot);
    cudaGetSymbolAddress((void**)&ctxt,     g_ctxt);

    cudaFuncSetAttribute(gemmt, cudaFuncAttributeMaxDynamicSharedMemorySize, GSMEM);

    // ---- one-time prep: fp32 concat + tf32 [hi|lo] splits ----
    prep<<<(NQP*UU)/256, 256>>>(dec_Whh, W2_W, fc_W, dec_bhh, W2_b, fc_b,
                                o2h_W, o2h_b, Wqgh, bqgh, Aemb);
    split2<<<(Sn*Bz*VIN)/256, 256>>>(x,       VIN,   xt,    Sn*Bz, VIN);
    split2<<<(G3U*VIN)/256, 256>>>(enc_Wih,   VIN,   Wiht,  G3U,   VIN);
    split2<<<(G3U*UU)/256, 256>>>(enc_Whh,    UU,    Whht,  G3U,   UU);
    split2<<<(NQP*UU)/256, 256>>>(Wqgh,       UU,    Wqght, NQP,   UU);
    split2<<<(G3U*UU)/256, 256>>>(dec_Wih,    UU+EE, Wdct,  G3U,   UU);
    split2<<<(G3U*EE)/256, 256>>>(dec_Wih+UU, UU+EE, Wdet,  G3U,   EE);
    split2<<<(UU*UU)/256, 256>>>(W1_W,        UU,    W1t,   UU,    UU);
    split2<<<(VOUTn*EE)/256, 256>>>(Aemb,     EE,    Aembt, VOUTn, EE);
    init_all<<<(int)(((size_t)Sn*Bz*KL_U/4)/256), 256>>>(
        (float4*)enc_out, (float4*)eot, (float4*)h, (float4*)ht, (float4*)out, idx);

    // emb->gi table: T[128,3U] = Aemb @ dec_Wih_emb^T + dec_bih
    gemmt<<<dim3(G3U/128, 1, 1), 256, GSMEM>>>(Aembt, Wdet, dec_bih, T,
                                        VOUTn, G3U, EE, 1, nullptr, -1);
    // encoder input gates, all steps (skip fully-masked 128-row tiles)
    gemmt<<<dim3(G3U/128, (Sn*Bz)/128, 1), 256, GSMEM>>>(xt, Wiht, enc_bih, gi_enc,
                                        Sn*Bz, G3U, VIN, 1, x_len, -1);

    // ---- Encoder: 64 sequential GRU steps (active-suffix only) ----
    for (int t = 0; t < Sn; t++) {
        gemmt<<<dim3(G3U/128, Bz/128, GHKS), 256, GSMEM>>>(ht, Whht, enc_bhh, ghp,
                                        Bz, G3U, UU, GHKS, x_len, t);
        enc_gate<<<(Bz*UU/4)/256, 256>>>(gi_enc + (size_t)t*Bz*G3U, ghp, h, ht,
                                         enc_out + (size_t)t*Bz*UU,
                                         eot + (size_t)t*Bz*KL_U, x_len, t);
    }

    // enc_proj = enc_out @ W1^T + b
    gemmt<<<dim3(UU/128, (Sn*Bz)/128, 1), 256, GSMEM>>>(eot, W1t, W1_b, enc_proj,
                                        Sn*Bz, UU, UU, 1, x_len, -1);

    // ---- Decoder: 24 steps; [gh|q|pred] one GEMM; pred_{k-1} fused into attn ----
    for (int k = 1; k <= TDEC - 1; k++) {
        gemmt<<<dim3(NQP/128, Bz/128, QGHKS), 256, GSMEM>>>(ht, Wqght, bqgh, qghp,
                                        Bz, NQP, UU, QGHKS, nullptr, -1);
        fused_attn<<<Bz, 256>>>(qghp, enc_proj, enc_out, V_W, V_b, W1_b,
                                x_len, ctxt,
                                (k >= 2) ? out + (size_t)(k-1)*Bz*VOUTn : nullptr,
                                idx);
        gemmt<<<dim3(G3U/128, Bz/128, GIKS), 256, GSMEM>>>(ctxt, Wdct, zerob, gip,
                                        Bz, G3U, UU, GIKS, nullptr, -1);
        dec_gate<<<(Bz*UU/4)/256, 256>>>(gip, qghp, T, idx, h, ht);
    }
    // final pred: fc(h_24) = out[24]
    gemmt<<<dim3(NQP/128, Bz/128, QGHKS), 256, GSMEM>>>(ht, Wqght, bqgh, qghp,
                                        Bz, NQP, UU, QGHKS, nullptr, -1);
    pred_argmax<<<Bz, 128>>>(qghp, out + (size_t)(TDEC-1)*Bz*VOUTn, idx);
}

// round 17
// speedup vs baseline: 1.2420x; 1.1017x over previous
#include <cuda_runtime.h>
#include <math.h>

typedef unsigned long long ull;
typedef unsigned int u32;

#define Sn    64
#define Bz    256
#define VIN   128
#define VOUTn 128
#define UU    1024
#define EE    512
#define TDEC  25
#define G3U   3072
#define NQP   4224            // [gh(3072) | q(1024) | pred(128)]
#define GHKS  3
#define GIKS  3
#define QGHKS 2
#define KL_U   (2*UU)         // tf32 limb storage [hi|lo] along K
#define KL_VIN (2*VIN)
#define KL_E   (2*EE)
#define STAGEB 49152          // A_hi 8K + A_lo 8K + W_hi 16K + W_lo 16K
#define GSMEM  (2*STAGEB)     // 96 KB -> 2 CTAs/SM

// ---------------- fp32 scratch ----------------
__device__ __align__(16) float g_gi_enc[(size_t)Sn*Bz*G3U];
__device__ __align__(16) float g_enc_out[(size_t)Sn*Bz*UU];
__device__ __align__(16) float g_enc_proj[(size_t)Sn*Bz*UU];
__device__ __align__(16) float g_h[Bz*UU];
__device__ __align__(16) float g_ghp[(size_t)GHKS*Bz*G3U];
__device__ __align__(16) float g_gip[(size_t)GIKS*Bz*G3U];
__device__ __align__(16) float g_qghp[(size_t)QGHKS*Bz*NQP];
__device__ int   g_idx[Bz];
__device__ __align__(16) float g_Wqgh[(size_t)NQP*UU];
__device__ __align__(16) float g_bqgh[NQP];
__device__ __align__(16) float g_T[(size_t)VOUTn*G3U];
__device__ __align__(16) float g_Aemb[VOUTn*EE];
__device__ __align__(16) float g_zero[NQP];

// ---------------- tf32 limb scratch ([hi|lo] concatenated along K) --------------
__device__ __align__(16) float g_xt   [(size_t)Sn*Bz*KL_VIN];
__device__ __align__(16) float g_Wiht [(size_t)G3U*KL_VIN];
__device__ __align__(16) float g_Whht [(size_t)G3U*KL_U];
__device__ __align__(16) float g_Wqght[(size_t)NQP*KL_U];
__device__ __align__(16) float g_Wdct [(size_t)G3U*KL_U];
__device__ __align__(16) float g_Wdet [(size_t)G3U*KL_E];
__device__ __align__(16) float g_W1t  [(size_t)UU*KL_U];
__device__ __align__(16) float g_Aembt[(size_t)VOUTn*KL_E];
__device__ __align__(16) float g_ht   [(size_t)Bz*KL_U];
__device__ __align__(16) float g_eot  [(size_t)Sn*Bz*KL_U];
__device__ __align__(16) float g_ctxt [(size_t)Bz*KL_U];

// ---------------- fast (~1e-7) transcendentals ----------------
__device__ __forceinline__ float f_ex2(float x){ float r; asm("ex2.approx.f32 %0, %1;" : "=f"(r) : "f"(x)); return r; }
__device__ __forceinline__ float f_rcp(float x){ float r; asm("rcp.approx.f32 %0, %1;" : "=f"(r) : "f"(x)); return r; }
__device__ __forceinline__ float fsigm(float x){ return f_rcp(1.f + f_ex2(-1.4426950408889634f*x)); }
__device__ __forceinline__ float ftanh(float x){ return 1.f - 2.f*f_rcp(1.f + f_ex2(2.8853900817779268f*x)); }

__device__ __forceinline__ float tf32f(float a) {
    u32 u; asm("cvt.rna.tf32.f32 %0, %1;" : "=r"(u) : "f"(a));
    return __uint_as_float(u);
}
__device__ __forceinline__ u32 s2u(const void* p) {
    u32 a; asm("{ .reg .u64 t; cvta.to.shared.u64 t, %1; cvt.u32.u64 %0, t; }" : "=r"(a) : "l"(p));
    return a;
}
__device__ __forceinline__ void cpa16(u32 dst, const void* src) {
    asm volatile("cp.async.cg.shared.global [%0], [%1], 16;" :: "r"(dst), "l"(src));
}
#define CP_COMMIT() asm volatile("cp.async.commit_group;" ::: "memory")
#define CP_WAIT1()  asm volatile("cp.async.wait_group 1;" ::: "memory")
#define CP_WAIT0()  asm volatile("cp.async.wait_group 0;" ::: "memory")

#define LDMX4(r0, r1, r2, r3, addr) \
    asm volatile("ldmatrix.sync.aligned.m8n8.x4.shared.b16 {%0,%1,%2,%3}, [%4];" \
        : "=r"(r0), "=r"(r1), "=r"(r2), "=r"(r3) : "r"(addr))

#define MMATF(d, a, b0, b1) \
    asm volatile("mma.sync.aligned.m16n8k8.row.col.f32.tf32.tf32.f32 " \
        "{%0,%1,%2,%3}, {%4,%5,%6,%7}, {%8,%9}, {%0,%1,%2,%3};" \
        : "+f"((d)[0]), "+f"((d)[1]), "+f"((d)[2]), "+f"((d)[3]) \
        : "r"((a)[0]), "r"((a)[1]), "r"((a)[2]), "r"((a)[3]), "r"(b0), "r"(b1))

// ------- tf32 limb GEMM: C[M,N] = A@W^T in fp32-grade precision (3xTF32) ---------
// A, W stored [hi|lo] along K (row stride 2K). Per 32-k window, stage A_hi/A_lo/
// W_hi/W_lo tiles via cp.async (2-stage) and accumulate hi*hi + hi*lo + lo*hi.
// 64x128 tile/CTA (2 CTAs/SM), 256 thr (8 warps 2x4), warp 32x32, m16n8k8 tf32.
// grid=(N/128, M/64, KS); slice z -> C + z*M*N over its window range.
// sorted-x_len early exit: tstep>=0: rows=batch; tstep<0: rows=s*256+b.
__global__ void __launch_bounds__(256, 2) gemmt(
    const float* __restrict__ A, const float* __restrict__ W,
    const float* __restrict__ bias, float* __restrict__ C,
    int M, int N, int K, int KS,
    const int* __restrict__ x_len, int tstep)
{
    const int bm = blockIdx.y * 64;
    if (x_len) {
        int t_eff = (tstep >= 0) ? tstep : (bm >> 8);
        int b_hi  = (tstep >= 0) ? (bm + 63) : ((bm & 255) + 63);
        if (x_len[b_hi] <= t_eff) return;
    }
    extern __shared__ __align__(16) char sm[];
    const u32 sb = s2u(sm);

    const int tid  = threadIdx.x;
    const int wid  = tid >> 5;
    const int lane = tid & 31;
    const int wm   = (wid >> 2) << 5;        // 0 / 32
    const int wn   = (wid & 3) << 5;         // 0..96
    const int bn   = blockIdx.x * 128;

    const int z  = blockIdx.z;
    const int NW = K >> 5;                   // 32-k windows
    const int w0 = (NW * z) / KS, w1 = (NW * (z + 1)) / KS;
    C += (size_t)z * M * N;

    float acc[2][4][4];
    #pragma unroll
    for (int i = 0; i < 2; i++)
        #pragma unroll
        for (int j = 0; j < 4; j++)
            #pragma unroll
            for (int r = 0; r < 4; r++) acc[i][j][r] = 0.f;

    const int rowA = tid >> 2;                // 0..63, 2 chunks each
    const int chA  = (tid & 3) << 1;
    const int rowW = tid >> 1;                // 0..127, 4 chunks each
    const int chW  = (tid & 1) << 2;
    const int lr15 = lane & 15;
    const int lc16 = lane >> 4;               // 0/1

    const float* gArow = A + (size_t)(bm + rowA) * (2 * K);
    const float* gWrow = W + (size_t)(bn + rowW) * (2 * K);
    const int soA = rowA * 128, swA = rowA & 7;
    const int soW = rowW * 128, swW = rowW & 7;

    // stage window w into pipeline stage s (A_hi @0, A_lo @8K, W_hi @16K, W_lo @32K)
    auto stage = [&](int s, int w) {
        const u32 base = sb + s * STAGEB;
        const uint4* ah = (const uint4*)(gArow + (w << 5));
        const uint4* al = (const uint4*)(gArow + K + (w << 5));
        #pragma unroll
        for (int c = 0; c < 2; c++) {
            int ch = chA + c;
            int so = soA + ((ch ^ swA) << 4);
            cpa16(base + so,        ah + ch);
            cpa16(base + 8192 + so, al + ch);
        }
        const uint4* wh = (const uint4*)(gWrow + (w << 5));
        const uint4* wl = (const uint4*)(gWrow + K + (w << 5));
        #pragma unroll
        for (int c = 0; c < 4; c++) {
            int ch = chW + c;
            int so = soW + ((ch ^ swW) << 4);
            cpa16(base + 16384 + so, wh + ch);
            cpa16(base + 32768 + so, wl + ch);
        }
    };

    auto compute = [&](int s) {
        const u32 base = sb + s * STAGEB;
        #pragma unroll
        for (int kk = 0; kk < 4; kk++) {
            u32 bH[2][4], bL[2][4];
            #pragma unroll
            for (int g = 0; g < 2; g++) {
                int row = wn + (g << 4) + lr15;
                int ch  = ((kk << 1) + lc16) ^ (row & 7);
                u32 off = row * 128 + (ch << 4);
                LDMX4(bH[g][0], bH[g][1], bH[g][2], bH[g][3], base + 16384 + off);
                LDMX4(bL[g][0], bL[g][1], bL[g][2], bL[g][3], base + 32768 + off);
            }
            #pragma unroll
            for (int mt = 0; mt < 2; mt++) {
                int row = wm + (mt << 4) + lr15;
                int ch  = ((kk << 1) + lc16) ^ (row & 7);
                u32 off = row * 128 + (ch << 4);
                u32 aH[4], aL[4];
                LDMX4(aH[0], aH[1], aH[2], aH[3], base + off);
                LDMX4(aL[0], aL[1], aL[2], aL[3], base + 8192 + off);
                #pragma unroll
                for (int nt = 0; nt < 4; nt++) {
                    int g = nt >> 1, sub = nt & 1;
                    MMATF(acc[mt][nt], aH, bH[g][sub], bH[g][2 + sub]);
                    MMATF(acc[mt][nt], aH, bL[g][sub], bL[g][2 + sub]);
                    MMATF(acc[mt][nt], aL, bH[g][sub], bH[g][2 + sub]);
                }
            }
        }
    };

    const int nw = w1 - w0;
    stage(0, w0); CP_COMMIT();
    for (int i = 0; i < nw; i++) {
        if (i + 1 < nw) { stage((i + 1) & 1, w0 + i + 1); CP_COMMIT(); CP_WAIT1(); }
        else            { CP_WAIT0(); }
        __syncthreads();
        compute(i & 1);
        __syncthreads();
    }

    // ---- epilogue: fp32 store (+bias on slice 0) ----
    const int er = lane >> 2;                 // 0..7
    const int ec = (lane & 3) << 1;           // 0,2,4,6
    #pragma unroll
    for (int mt = 0; mt < 2; mt++) {
        int row0 = bm + wm + (mt << 4) + er;
        #pragma unroll
        for (int nt = 0; nt < 4; nt++) {
            int col = bn + wn + (nt << 3) + ec;
            float b0 = 0.f, b1 = 0.f;
            if (z == 0) { b0 = bias[col]; b1 = bias[col + 1]; }
            *(float2*)(C + (size_t)row0 * N + col) =
                make_float2(acc[mt][nt][0] + b0, acc[mt][nt][1] + b1);
            *(float2*)(C + (size_t)(row0 + 8) * N + col) =
                make_float2(acc[mt][nt][2] + b0, acc[mt][nt][3] + b1);
        }
    }
}

// ---------------- merged tf32 [hi|lo] splitter (all 8 tensors, 1 launch) --------
struct SplitJobs {
    const float* src[8];
    float*       dst[8];
    int lds[8];
    int C[8];
    long long off[9];
};

__global__ void split_all(SplitJobs J)
{
    long long i = (long long)blockIdx.x * 256 + threadIdx.x;
    if (i >= J.off[8]) return;
    int j = 0;
    #pragma unroll
    for (int k = 1; k < 8; k++) if (i >= J.off[k]) j = k;
    long long l = i - J.off[j];
    int C = J.C[j];
    long long r = l / C;
    int c = (int)(l - r * C);
    float a  = J.src[j][r * J.lds[j] + c];
    float hi = tf32f(a);
    float lo = tf32f(a - hi);
    float* d = J.dst[j] + r * 2 * C;
    d[c] = hi; d[C + c] = lo;
}

__device__ __forceinline__ void split4l(float* rowb, int Kc, int u, float4 v) {
    float4 hi, lo;
    hi.x = tf32f(v.x); lo.x = tf32f(v.x - hi.x);
    hi.y = tf32f(v.y); lo.y = tf32f(v.y - hi.y);
    hi.z = tf32f(v.z); lo.z = tf32f(v.z - hi.z);
    hi.w = tf32f(v.w); lo.w = tf32f(v.w - hi.w);
    *(float4*)(rowb + u)      = hi;
    *(float4*)(rowb + Kc + u) = lo;
}

// ---------------- encoder GRU gate ----------------
__global__ void enc_gate(const float* __restrict__ gi, const float* __restrict__ ghp,
                         float* __restrict__ h, float* __restrict__ ht,
                         float* __restrict__ enc_out_t, float* __restrict__ eot_t,
                         const int* __restrict__ x_len, int t)
{
    int i = blockIdx.x * blockDim.x + threadIdx.x;       // float4 index
    int b = i >> 8;
    if (t >= x_len[b]) return;
    int u = (i & 255) << 2;
    size_t base = (size_t)b * G3U + u;
    const size_t MN = (size_t)Bz * G3U;
    float4 gr = *(const float4*)(ghp + base);
    float4 gz = *(const float4*)(ghp + base + UU);
    float4 gn = *(const float4*)(ghp + base + 2*UU);
    #pragma unroll
    for (int s = 1; s < GHKS; s++) {
        float4 a = *(const float4*)(ghp + s*MN + base);
        float4 c = *(const float4*)(ghp + s*MN + base + UU);
        float4 d = *(const float4*)(ghp + s*MN + base + 2*UU);
        gr.x+=a.x; gr.y+=a.y; gr.z+=a.z; gr.w+=a.w;
        gz.x+=c.x; gz.y+=c.y; gz.z+=c.z; gz.w+=c.w;
        gn.x+=d.x; gn.y+=d.y; gn.z+=d.z; gn.w+=d.w;
    }
    float4 ir = *(const float4*)(gi + base);
    float4 iz = *(const float4*)(gi + base + UU);
    float4 in = *(const float4*)(gi + base + 2*UU);
    float4 hv = *(const float4*)(h + (size_t)b*UU + u);
    float4 hn;
    {
        float r, z, n;
        r = fsigm(ir.x+gr.x); z = fsigm(iz.x+gz.x); n = ftanh(in.x + r*gn.x); hn.x = (1.f-z)*n + z*hv.x;
        r = fsigm(ir.y+gr.y); z = fsigm(iz.y+gz.y); n = ftanh(in.y + r*gn.y); hn.y = (1.f-z)*n + z*hv.y;
        r = fsigm(ir.z+gr.z); z = fsigm(iz.z+gz.z); n = ftanh(in.z + r*gn.z); hn.z = (1.f-z)*n + z*hv.z;
        r = fsigm(ir.w+gr.w); z = fsigm(iz.w+gz.w); n = ftanh(in.w + r*gn.w); hn.w = (1.f-z)*n + z*hv.w;
    }
    *(float4*)(h + (size_t)b*UU + u)         = hn;
    *(float4*)(enc_out_t + (size_t)b*UU + u) = hn;
    split4l(ht    + (size_t)b*KL_U, UU, u, hn);
    split4l(eot_t + (size_t)b*KL_U, UU, u, hn);
}

// ---------------- decoder GRU gate ----------------
__global__ void dec_gate(const float* __restrict__ gip, const float* __restrict__ qghp,
                         const float* __restrict__ T, const int* __restrict__ idx,
                         float* __restrict__ h, float* __restrict__ ht)
{
    int i = blockIdx.x * blockDim.x + threadIdx.x;
    int b = i >> 8;
    int u = (i & 255) << 2;
    size_t gbase = (size_t)b * G3U + u;
    const size_t MN3 = (size_t)Bz * G3U;
    const float* tb = T + (size_t)idx[b] * G3U + u;
    float4 ir = *(const float4*)(tb);
    float4 iz = *(const float4*)(tb + UU);
    float4 in = *(const float4*)(tb + 2*UU);
    #pragma unroll
    for (int s = 0; s < GIKS; s++) {
        float4 a = *(const float4*)(gip + s*MN3 + gbase);
        float4 c = *(const float4*)(gip + s*MN3 + gbase + UU);
        float4 d = *(const float4*)(gip + s*MN3 + gbase + 2*UU);
        ir.x+=a.x; ir.y+=a.y; ir.z+=a.z; ir.w+=a.w;
        iz.x+=c.x; iz.y+=c.y; iz.z+=c.z; iz.w+=c.w;
        in.x+=d.x; in.y+=d.y; in.z+=d.z; in.w+=d.w;
    }
    size_t qbase = (size_t)b * NQP + u;
    const size_t MNq = (size_t)Bz * NQP;
    float4 gr = make_float4(0,0,0,0), gz = gr, gn = gr;
    #pragma unroll
    for (int s = 0; s < QGHKS; s++) {
        float4 a = *(const float4*)(qghp + s*MNq + qbase);
        float4 c = *(const float4*)(qghp + s*MNq + qbase + UU);
        float4 d = *(const float4*)(qghp + s*MNq + qbase + 2*UU);
        gr.x+=a.x; gr.y+=a.y; gr.z+=a.z; gr.w+=a.w;
        gz.x+=c.x; gz.y+=c.y; gz.z+=c.z; gz.w+=c.w;
        gn.x+=d.x; gn.y+=d.y; gn.z+=d.z; gn.w+=d.w;
    }
    float4 hv = *(const float4*)(h + (size_t)b*UU + u);
    float4 hn;
    {
        float r, z, n;
        r = fsigm(ir.x+gr.x); z = fsigm(iz.x+gz.x); n = ftanh(in.x + r*gn.x); hn.x = (1.f-z)*n + z*hv.x;
        r = fsigm(ir.y+gr.y); z = fsigm(iz.y+gz.y); n = ftanh(in.y + r*gn.y); hn.y = (1.f-z)*n + z*hv.y;
        r = fsigm(ir.z+gr.z); z = fsigm(iz.z+gz.z); n = ftanh(in.z + r*gn.z); hn.z = (1.f-z)*n + z*hv.z;
        r = fsigm(ir.w+gr.w); z = fsigm(iz.w+gz.w); n = ftanh(in.w + r*gn.w); hn.w = (1.f-z)*n + z*hv.w;
    }
    *(float4*)(h + (size_t)b*UU + u) = hn;
    split4l(ht + (size_t)b*KL_U, UU, u, hn);
}

// ------- fused attention (+ pred/argmax of prev step); writes ctx limbs ---------
__global__ void __launch_bounds__(256) fused_attn(
    const float* __restrict__ qghp, const float* __restrict__ enc_proj,
    const float* __restrict__ enc_out,
    const float* __restrict__ V_W, const float* __restrict__ V_b,
    const float* __restrict__ W1_b, const int* __restrict__ x_len,
    float* __restrict__ ctxt,
    float* __restrict__ out_t, int* __restrict__ idx)
{
    __shared__ float qs[UU];
    __shared__ float vs[UU];
    __shared__ float wb[UU];
    __shared__ float lg[Sn];
    __shared__ float sv[VOUTn];
    __shared__ int   si[VOUTn];
    const int b = blockIdx.x, tid = threadIdx.x;
    const int w = tid >> 5, lane = tid & 31;
    const size_t MNq = (size_t)Bz * NQP;
    const size_t qoff = (size_t)b * NQP + 3*UU;

    if (out_t) {
        if (tid < VOUTn) {
            size_t base = (size_t)b * NQP + 4096 + tid;
            float v = 0.f;
            #pragma unroll
            for (int s = 0; s < QGHKS; s++) v += qghp[s*MNq + base];
            out_t[(size_t)b * VOUTn + tid] = v;
            sv[tid] = v; si[tid] = tid;
        }
        __syncthreads();
        #pragma unroll
        for (int off = 64; off; off >>= 1) {
            if (tid < off) {
                float v2 = sv[tid+off]; int i2 = si[tid+off];
                if (v2 > sv[tid] || (v2 == sv[tid] && i2 < si[tid])) { sv[tid] = v2; si[tid] = i2; }
            }
            __syncthreads();
        }
        if (tid == 0) idx[b] = si[0];
    }

    #pragma unroll
    for (int k = 0; k < 4; k++) {
        int u = tid + 256*k;
        float qv = 0.f;
        #pragma unroll
        for (int s = 0; s < QGHKS; s++) qv += qghp[s*MNq + qoff + u];
        qs[u] = qv;
        vs[u] = V_W[u];
        wb[u] = W1_b[u];
    }
    __syncthreads();

    const int L = x_len[b];
    for (int s = w; s < L; s += 8) {
        const float4* ep = (const float4*)(enc_proj + ((size_t)s * Bz + b) * UU);
        const float4* q4 = (const float4*)qs;
        const float4* v4 = (const float4*)vs;
        float sum = 0.f;
        #pragma unroll
        for (int it = 0; it < 8; it++) {
            int u = lane + 32*it;
            float4 e = ep[u], qq = q4[u], vv = v4[u];
            sum += ftanh(e.x + qq.x) * vv.x + ftanh(e.y + qq.y) * vv.y
                 + ftanh(e.z + qq.z) * vv.z + ftanh(e.w + qq.w) * vv.w;
        }
        #pragma unroll
        for (int off = 16; off; off >>= 1)
            sum += __shfl_down_sync(0xffffffffu, sum, off);
        if (lane == 0) lg[s] = sum + V_b[0];
    }
    if (w == 0 && L < Sn) {          // masked s: enc_proj row == W1_b analytically
        const float4* q4 = (const float4*)qs;
        const float4* v4 = (const float4*)vs;
        const float4* w4 = (const float4*)wb;
        float sum = 0.f;
        #pragma unroll
        for (int it = 0; it < 8; it++) {
            int u = lane + 32*it;
            float4 e = w4[u], qq = q4[u], vv = v4[u];
            sum += ftanh(e.x + qq.x) * vv.x + ftanh(e.y + qq.y) * vv.y
                 + ftanh(e.z + qq.z) * vv.z + ftanh(e.w + qq.w) * vv.w;
        }
        #pragma unroll
        for (int off = 16; off; off >>= 1)
            sum += __shfl_down_sync(0xffffffffu, sum, off);
        if (lane == 0) {
            float c = sum + V_b[0];
            for (int s = L; s < Sn; s++) lg[s] = c;
        }
    }
    __syncthreads();

    if (w == 0) {
        float v0 = lg[lane], v1 = lg[lane + 32];
        float mx = fmaxf(v0, v1);
        #pragma unroll
        for (int off = 16; off; off >>= 1)
            mx = fmaxf(mx, __shfl_xor_sync(0xffffffffu, mx, off));
        float e0 = f_ex2(1.4426950408889634f * (v0 - mx));
        float e1 = f_ex2(1.4426950408889634f * (v1 - mx));
        float smv = e0 + e1;
        #pragma unroll
        for (int off = 16; off; off >>= 1)
            smv += __shfl_xor_sync(0xffffffffu, smv, off);
        float inv = f_rcp(smv);
        lg[lane]      = e0 * inv;
        lg[lane + 32] = e1 * inv;
    }
    __syncthreads();

    float4 c4 = make_float4(0,0,0,0);
    const int u = tid << 2;
    for (int s = 0; s < L; s++) {
        float a = lg[s];
        float4 eo = *(const float4*)(enc_out + ((size_t)s * Bz + b) * UU + u);
        c4.x += a * eo.x; c4.y += a * eo.y; c4.z += a * eo.z; c4.w += a * eo.w;
    }
    split4l(ctxt + (size_t)b * KL_U, UU, u, c4);
}

// ---------------- final pred: sum partials + write + argmax ----------------
__global__ void pred_argmax(const float* __restrict__ qghp,
                            float* __restrict__ out_t, int* __restrict__ idx)
{
    int b = blockIdx.x;
    int t = threadIdx.x;            // 128 threads
    const size_t MNq = (size_t)Bz * NQP;
    size_t base = (size_t)b * NQP + 4096 + t;
    float v = 0.f;
    #pragma unroll
    for (int s = 0; s < QGHKS; s++) v += qghp[s*MNq + base];
    out_t[(size_t)b * VOUTn + t] = v;

    __shared__ float sv[VOUTn];
    __shared__ int   si[VOUTn];
    sv[t] = v; si[t] = t;
    __syncthreads();
    #pragma unroll
    for (int off = 64; off; off >>= 1) {
        if (t < off) {
            float v2 = sv[t+off]; int i2 = si[t+off];
            if (v2 > sv[t] || (v2 == sv[t] && i2 < si[t])) { sv[t] = v2; si[t] = i2; }
        }
        __syncthreads();
    }
    if (t == 0) idx[b] = si[0];
}

// ---------------- one-time prep & init ----------------
__global__ void prep(const float* __restrict__ dec_Whh, const float* __restrict__ W2_W,
                     const float* __restrict__ fc_W,
                     const float* __restrict__ dec_bhh, const float* __restrict__ W2_b,
                     const float* __restrict__ fc_b,
                     const float* __restrict__ o2h_W,   const float* __restrict__ o2h_b,
                     float* __restrict__ Wqgh, float* __restrict__ bqgh,
                     float* __restrict__ Aemb)
{
    int i = blockIdx.x * 256 + threadIdx.x;          // 0 .. NQP*UU-1
    float wv;
    if (i < G3U*UU)            wv = dec_Whh[i];
    else if (i < (G3U+UU)*UU)  wv = W2_W[i - G3U*UU];
    else                       wv = fc_W[i - (G3U+UU)*UU];
    Wqgh[i] = wv;
    if (i < NQP) {
        float bv;
        if (i < G3U)           bv = dec_bhh[i];
        else if (i < G3U+UU)   bv = W2_b[i - G3U];
        else                   bv = fc_b[i - G3U - UU];
        bqgh[i] = bv;
    }
    if (i < VOUTn*EE) {
        int v = i / EE, e = i % EE;
        Aemb[i] = o2h_W[(size_t)e * VOUTn + v] + o2h_b[e];
    }
}

__global__ void init_all(float4* __restrict__ enc_out, float4* __restrict__ eot,
                         float4* __restrict__ h, float4* __restrict__ ht,
                         float4* __restrict__ out0, int* __restrict__ idx)
{
    size_t i = (size_t)blockIdx.x * 256 + threadIdx.x;   // over S*B*KL_U/4 float4s
    float4 zz = make_float4(0,0,0,0);
    eot[i] = zz;
    if (i < (size_t)Sn*Bz*UU/4) enc_out[i] = zz;
    if (i < Bz*UU/4)            h[i] = zz;
    if (i < Bz*KL_U/4)          ht[i] = zz;
    if (i < Bz*VOUTn/4)         out0[i] = ((i & 31) == 0) ? make_float4(1,0,0,0) : zz;
    if (i < Bz)                 idx[i] = 0;
}

// ---------------- driver ----------------
extern "C" void kernel_launch(void* const* d_in, const int* in_sizes, int n_in,
                              void* d_out, int out_size)
{
    const float* x       = (const float*)d_in[0];
    const int*   x_len   = (const int*)  d_in[1];
    const float* enc_Wih = (const float*)d_in[2];
    const float* enc_Whh = (const float*)d_in[3];
    const float* enc_bih = (const float*)d_in[4];
    const float* enc_bhh = (const float*)d_in[5];
    const float* dec_Wih = (const float*)d_in[6];
    const float* dec_Whh = (const float*)d_in[7];
    const float* dec_bih = (const float*)d_in[8];
    const float* dec_bhh = (const float*)d_in[9];
    const float* o2h_W   = (const float*)d_in[10];
    const float* o2h_b   = (const float*)d_in[11];
    const float* fc_W    = (const float*)d_in[12];
    const float* fc_b    = (const float*)d_in[13];
    const float* W1_W    = (const float*)d_in[14];
    const float* W1_b    = (const float*)d_in[15];
    const float* W2_W    = (const float*)d_in[16];
    const float* W2_b    = (const float*)d_in[17];
    const float* V_W     = (const float*)d_in[18];
    const float* V_b     = (const float*)d_in[19];
    float* out = (float*)d_out;

    float *gi_enc, *enc_out, *enc_proj, *h, *ghp, *gip, *qghp;
    float *Wqgh, *bqgh, *T, *Aemb, *zerob;
    float *xt, *Wiht, *Whht, *Wqght, *Wdct, *Wdet, *W1t, *Aembt, *ht, *eot, *ctxt;
    int* idx;
    cudaGetSymbolAddress((void**)&gi_enc,   g_gi_enc);
    cudaGetSymbolAddress((void**)&enc_out,  g_enc_out);
    cudaGetSymbolAddress((void**)&enc_proj, g_enc_proj);
    cudaGetSymbolAddress((void**)&h,        g_h);
    cudaGetSymbolAddress((void**)&ghp,      g_ghp);
    cudaGetSymbolAddress((void**)&gip,      g_gip);
    cudaGetSymbolAddress((void**)&qghp,     g_qghp);
    cudaGetSymbolAddress((void**)&idx,      g_idx);
    cudaGetSymbolAddress((void**)&Wqgh,     g_Wqgh);
    cudaGetSymbolAddress((void**)&bqgh,     g_bqgh);
    cudaGetSymbolAddress((void**)&T,        g_T);
    cudaGetSymbolAddress((void**)&Aemb,     g_Aemb);
    cudaGetSymbolAddress((void**)&zerob,    g_zero);
    cudaGetSymbolAddress((void**)&xt,       g_xt);
    cudaGetSymbolAddress((void**)&Wiht,     g_Wiht);
    cudaGetSymbolAddress((void**)&Whht,     g_Whht);
    cudaGetSymbolAddress((void**)&Wqght,    g_Wqght);
    cudaGetSymbolAddress((void**)&Wdct,     g_Wdct);
    cudaGetSymbolAddress((void**)&Wdet,     g_Wdet);
    cudaGetSymbolAddress((void**)&W1t,      g_W1t);
    cudaGetSymbolAddress((void**)&Aembt,    g_Aembt);
    cudaGetSymbolAddress((void**)&ht,       g_ht);
    cudaGetSymbolAddress((void**)&eot,      g_eot);
    cudaGetSymbolAddress((void**)&ctxt,     g_ctxt);

    cudaFuncSetAttribute(gemmt, cudaFuncAttributeMaxDynamicSharedMemorySize, GSMEM);

    // ---- one-time prep: fp32 concat, then ALL tf32 [hi|lo] splits in 1 launch ----
    prep<<<(NQP*UU)/256, 256>>>(dec_Whh, W2_W, fc_W, dec_bhh, W2_b, fc_b,
                                o2h_W, o2h_b, Wqgh, bqgh, Aemb);
    SplitJobs J;
    const float* srcs[8] = { x, enc_Wih, enc_Whh, Wqgh, dec_Wih, dec_Wih + UU, W1_W, Aemb };
    float*       dsts[8] = { xt, Wiht, Whht, Wqght, Wdct, Wdet, W1t, Aembt };
    int ldss[8] = { VIN, VIN, UU, UU, UU+EE, UU+EE, UU, EE };
    int Cs[8]   = { VIN, VIN, UU, UU, UU,    EE,    UU, EE };
    long long Rs[8] = { (long long)Sn*Bz, G3U, G3U, NQP, G3U, G3U, UU, VOUTn };
    long long acc = 0;
    for (int j = 0; j < 8; j++) {
        J.src[j] = srcs[j]; J.dst[j] = dsts[j];
        J.lds[j] = ldss[j]; J.C[j] = Cs[j];
        J.off[j] = acc; acc += Rs[j] * Cs[j];
    }
    J.off[8] = acc;
    split_all<<<(int)((acc + 255) / 256), 256>>>(J);
    init_all<<<(int)(((size_t)Sn*Bz*KL_U/4)/256), 256>>>(
        (float4*)enc_out, (float4*)eot, (float4*)h, (float4*)ht, (float4*)out, idx);

    // emb->gi table: T[128,3U] = Aemb @ dec_Wih_emb^T + dec_bih
    gemmt<<<dim3(G3U/128, VOUTn/64, 1), 256, GSMEM>>>(Aembt, Wdet, dec_bih, T,
                                        VOUTn, G3U, EE, 1, nullptr, -1);
    // encoder input gates, all steps (skip fully-masked 64-row tiles)
    gemmt<<<dim3(G3U/128, (Sn*Bz)/64, 1), 256, GSMEM>>>(xt, Wiht, enc_bih, gi_enc,
                                        Sn*Bz, G3U, VIN, 1, x_len, -1);

    // ---- Encoder: 64 sequential GRU steps (active-suffix only) ----
    for (int t = 0; t < Sn; t++) {
        gemmt<<<dim3(G3U/128, Bz/64, GHKS), 256, GSMEM>>>(ht, Whht, enc_bhh, ghp,
                                        Bz, G3U, UU, GHKS, x_len, t);
        enc_gate<<<(Bz*UU/4)/256, 256>>>(gi_enc + (size_t)t*Bz*G3U, ghp, h, ht,
                                         enc_out + (size_t)t*Bz*UU,
                                         eot + (size_t)t*Bz*KL_U, x_len, t);
    }

    // enc_proj = enc_out @ W1^T + b
    gemmt<<<dim3(UU/128, (Sn*Bz)/64, 1), 256, GSMEM>>>(eot, W1t, W1_b, enc_proj,
                                        Sn*Bz, UU, UU, 1, x_len, -1);

    // ---- Decoder: 24 steps; [gh|q|pred] one GEMM; pred_{k-1} fused into attn ----
    for (int k = 1; k <= TDEC - 1; k++) {
        gemmt<<<dim3(NQP/128, Bz/64, QGHKS), 256, GSMEM>>>(ht, Wqght, bqgh, qghp,
                                        Bz, NQP, UU, QGHKS, nullptr, -1);
        fused_attn<<<Bz, 256>>>(qghp, enc_proj, enc_out, V_W, V_b, W1_b,
                                x_len, ctxt,
                                (k >= 2) ? out + (size_t)(k-1)*Bz*VOUTn : nullptr,
                                idx);
        gemmt<<<dim3(G3U/128, Bz/64, GIKS), 256, GSMEM>>>(ctxt, Wdct, zerob, gip,
                                        Bz, G3U, UU, GIKS, nullptr, -1);
        dec_gate<<<(Bz*UU/4)/256, 256>>>(gip, qghp, T, idx, h, ht);
    }
    // final pred: fc(h_24) = out[24]
    gemmt<<<dim3(NQP/128, Bz/64, QGHKS), 256, GSMEM>>>(ht, Wqght, bqgh, qghp,
                                        Bz, NQP, UU, QGHKS, nullptr, -1);
    pred_argmax<<<Bz, 128>>>(qghp, out + (size_t)(TDEC-1)*Bz*VOUTn, idx);
}